// round 12
// baseline (speedup 1.0000x reference)
#include <cuda_runtime.h>
#include <cuda_bf16.h>
#include <math.h>
#include <stdint.h>

#define BB 128
#define TT 1024
#define HH 512
#define GG 1536
#define NCTA 128

// ---------------- device scratch (no allocation) ----------------
__device__ float g_xp[(size_t)BB * TT * GG];
__device__ __nv_bfloat16 g_xhi[(size_t)BB * TT * 256];
__device__ __nv_bfloat16 g_xlo[(size_t)BB * TT * 256];
__device__ __nv_bfloat16 g_h1hi[(size_t)BB * TT * HH];
__device__ __nv_bfloat16 g_h1lo[(size_t)BB * TT * HH];
__device__ __nv_bfloat16 g_w0hi[GG * 256], g_w0lo[GG * 256];
__device__ __nv_bfloat16 g_w1hi[GG * HH],  g_w1lo[GG * HH];
__device__ __nv_bfloat16 g_whhhi[2][16 * 96 * 512];
__device__ __nv_bfloat16 g_whhlo[2][16 * 96 * 512];
__device__ __nv_bfloat16 g_hbhi[2][BB * HH];
__device__ __nv_bfloat16 g_hblo[2][BB * HH];
// per-CTA progress flags: [mg][ng][pad 128B]; monotonic across launches/replays
__device__ unsigned g_flag[8][16][32];

// ---------------- PTX helpers (baseline PTX only) ----------------
__device__ __forceinline__ uint32_t smem_u32(const void* p) {
    uint32_t a;
    asm("{ .reg .u64 t; cvta.to.shared.u64 t, %1; cvt.u32.u64 %0, t; }" : "=r"(a) : "l"(p));
    return a;
}

#define CP16(dst, src) \
    asm volatile("cp.async.cg.shared.global [%0], [%1], 16;" :: "r"(dst), "l"(src))
#define CPCOMMIT() asm volatile("cp.async.commit_group;")
#define CPWAIT0()  asm volatile("cp.async.wait_group 0;")
#define CPWAIT1()  asm volatile("cp.async.wait_group 1;")

#define LDSM4(r, a) \
    asm volatile("ldmatrix.sync.aligned.m8n8.x4.shared.b16 {%0,%1,%2,%3}, [%4];" \
        : "=r"((r)[0]), "=r"((r)[1]), "=r"((r)[2]), "=r"((r)[3]) : "r"(a))
#define LDSM2(r, a) \
    asm volatile("ldmatrix.sync.aligned.m8n8.x2.shared.b16 {%0,%1}, [%2];" \
        : "=r"((r)[0]), "=r"((r)[1]) : "r"(a))

#define MMA16816(c, a, b) \
    asm volatile("mma.sync.aligned.m16n8k16.row.col.f32.bf16.bf16.f32 " \
        "{%0,%1,%2,%3}, {%4,%5,%6,%7}, {%8,%9}, {%0,%1,%2,%3};" \
        : "+f"((c)[0]), "+f"((c)[1]), "+f"((c)[2]), "+f"((c)[3]) \
        : "r"((a)[0]), "r"((a)[1]), "r"((a)[2]), "r"((a)[3]), "r"((b)[0]), "r"((b)[1]))

__device__ __forceinline__ void relstore(unsigned* p, unsigned v) {
    asm volatile("st.release.gpu.u32 [%0], %1;" :: "l"(p), "r"(v) : "memory");
}
__device__ __forceinline__ unsigned acqload(unsigned* p) {
    unsigned v;
    asm volatile("ld.acquire.gpu.u32 %0, [%1];" : "=r"(v) : "l"(p) : "memory");
    return v;
}

// ---------------- conversions ----------------
__global__ void split_f32(const float* __restrict__ src, size_t n,
                          __nv_bfloat16* __restrict__ hi, __nv_bfloat16* __restrict__ lo) {
    size_t i = (size_t)blockIdx.x * blockDim.x + threadIdx.x;
    if (i < n) {
        float v = src[i];
        __nv_bfloat16 h = __float2bfloat16(v);
        hi[i] = h;
        lo[i] = __float2bfloat16(v - __bfloat162float(h));
    }
}

// reorder Whh [1536,512] -> [16 ng][96][512]  (row j: gate j>>5, col j&31)
__global__ void split_whh(const float* __restrict__ W,
                          __nv_bfloat16* __restrict__ hi, __nv_bfloat16* __restrict__ lo) {
    int i = blockIdx.x * 256 + threadIdx.x;
    int k = i & 511;
    int ro = i >> 9;
    int ng = ro / 96, j = ro % 96;
    int g = j >> 5, jj = j & 31;
    float v = W[(size_t)(g * 512 + ng * 32 + jj) * 512 + k];
    __nv_bfloat16 h = __float2bfloat16(v);
    hi[i] = h;
    lo[i] = __float2bfloat16(v - __bfloat162float(h));
}

// ---------------- mma.sync GEMM: fused 3-term, stage once per K-chunk ----------------
template <int K>
__global__ void __launch_bounds__(256) gemm_mma(
    const __nv_bfloat16* __restrict__ Ahi, const __nv_bfloat16* __restrict__ Alo,
    const __nv_bfloat16* __restrict__ Bhi, const __nv_bfloat16* __restrict__ Blo,
    const float* __restrict__ bias, float* __restrict__ C)
{
    extern __shared__ char smx[];
    const uint32_t sb = smem_u32(smx);
    const int tid = threadIdx.x, w = tid >> 5, lane = tid & 31;
    const int wm = w >> 2, wn = w & 3;
    const int m0 = blockIdx.y * 128, n0 = blockIdx.x * 128;

    float c[4][4][4];
#pragma unroll
    for (int i = 0; i < 4; i++)
#pragma unroll
        for (int j = 0; j < 4; j++)
#pragma unroll
            for (int q = 0; q < 4; q++) c[i][j][q] = 0.f;

    const int a_r  = (lane & 7) + ((lane >> 3) & 1) * 8;
    const int a_co = lane >> 4;
    const int b_r  = lane & 7;
    const int b_co = (lane >> 3) & 1;

    const int KC = K / 64;

    auto stage = [&](int kc, int buf) {
        uint32_t bb = sb + buf * 65536;
#pragma unroll
        for (int j = 0; j < 4; j++) {
            int idx = tid + j * 256;
            int r = idx >> 3, cc = idx & 7;
            uint32_t off = (uint32_t)(r * 128 + ((cc ^ (r & 7)) << 4));
            const size_t ao = (size_t)(m0 + r) * K + kc * 64 + cc * 8;
            const size_t bo = (size_t)(n0 + r) * K + kc * 64 + cc * 8;
            CP16(bb + off,         Ahi + ao);
            CP16(bb + 16384 + off, Alo + ao);
            CP16(bb + 32768 + off, Bhi + bo);
            CP16(bb + 49152 + off, Blo + bo);
        }
        CPCOMMIT();
    };

    stage(0, 0);
    if (KC > 1) stage(1, 1);
    for (int it = 0; it < KC; it++) {
        int buf = it % 3;
        if (it + 1 < KC) CPWAIT1(); else CPWAIT0();
        __syncthreads();

        uint32_t bb = sb + buf * 65536;
        const uint32_t AbH = bb + (wm * 64) * 128;
        const uint32_t AbL = bb + 16384 + (wm * 64) * 128;
        const uint32_t BbH = bb + 32768 + (wn * 32) * 128;
        const uint32_t BbL = bb + 49152 + (wn * 32) * 128;
#pragma unroll
        for (int kk = 0; kk < 4; kk++) {
            uint32_t ah[4][4], al[4][4];
            uint32_t asw = (uint32_t)(((2 * kk + a_co) ^ (a_r & 7)) << 4);
#pragma unroll
            for (int mt = 0; mt < 4; mt++) {
                LDSM4(ah[mt], AbH + (mt * 16 + a_r) * 128 + asw);
                LDSM4(al[mt], AbL + (mt * 16 + a_r) * 128 + asw);
            }
            uint32_t bsw = (uint32_t)(((2 * kk + b_co) ^ (b_r & 7)) << 4);
#pragma unroll
            for (int nt = 0; nt < 4; nt++) {
                uint32_t bh[2], bl[2];
                LDSM2(bh, BbH + (nt * 8 + b_r) * 128 + bsw);
                LDSM2(bl, BbL + (nt * 8 + b_r) * 128 + bsw);
#pragma unroll
                for (int mt = 0; mt < 4; mt++) {
                    MMA16816(c[mt][nt], ah[mt], bh);
                    MMA16816(c[mt][nt], al[mt], bh);
                    MMA16816(c[mt][nt], ah[mt], bl);
                }
            }
        }
        if (it + 2 < KC) stage(it + 2, (it + 2) % 3);
    }

#pragma unroll
    for (int nt = 0; nt < 4; nt++) {
        int col = n0 + wn * 32 + nt * 8 + (lane & 3) * 2;
        float2 bv = *(const float2*)&bias[col];
#pragma unroll
        for (int mt = 0; mt < 4; mt++) {
            int row = m0 + wm * 64 + mt * 16 + (lane >> 2);
            float2 v0 = { c[mt][nt][0] + bv.x, c[mt][nt][1] + bv.y };
            float2 v1 = { c[mt][nt][2] + bv.x, c[mt][nt][3] + bv.y };
            *(float2*)&C[(size_t)row * GG + col] = v0;
            *(float2*)&C[(size_t)(row + 8) * GG + col] = v1;
        }
    }
}

// ---------------- persistent mma.sync GRU layer, fragment-layout epilogue ----------------
// B gate-row mapping n = f*32 + nq*8 + b_r  =>  acc[0..2] are the r,z,n partials
// of the SAME output columns. kh=1 warps dump 12 floats (parity buffer) and run
// ahead; kh=0 warps pair-sync (bar 8+nq, 64 thr), reduce in regs, compute gates
// for their 4 fragment elements, write h, 128-thr bar, release.
__global__ void __launch_bounds__(256, 1) gru_mma(
    const float* __restrict__ xp,
    const __nv_bfloat16* __restrict__ Whi_g, const __nv_bfloat16* __restrict__ Wlo_g,
    const float* __restrict__ bhh,
    __nv_bfloat16* __restrict__ seqhi, __nv_bfloat16* __restrict__ seqlo)
{
    extern __shared__ char smx[];
    const uint32_t sb = smem_u32(smx);
    float* sbias = (float*)smx;                    // 96 floats
    const uint32_t W_HI = 512;
    const uint32_t W_LO = 512 + 98304;
    const uint32_t A_HI = 512 + 196608;
    const uint32_t A_LO = A_HI + 16384;
    float* dred = (float*)(smx + W_HI);            // parity x 128 x 13 floats (overlays W_HI)

    const int tid = threadIdx.x, w = tid >> 5, lane = tid & 31;
    const int nq = w & 3, kh = w >> 2;
    const int half = tid >> 7;                     // == kh
    const int ng = blockIdx.x & 15, mg = blockIdx.x >> 4;

    const unsigned base = g_flag[mg][ng][0];       // stable between launches

    // persistent W slice, swizzled
    const __nv_bfloat16* wh = Whi_g + (size_t)ng * 96 * 512;
    const __nv_bfloat16* wl = Wlo_g + (size_t)ng * 96 * 512;
    for (int idx = tid; idx < 6144; idx += 256) {
        int r = idx >> 6, cc = idx & 63;
        uint32_t off = (uint32_t)(r * 1024 + ((cc ^ (r & 7)) << 4));
        *(uint4*)(smx + W_HI + off) = *(const uint4*)(wh + r * 512 + cc * 8);
        *(uint4*)(smx + W_LO + off) = *(const uint4*)(wl + r * 512 + cc * 8);
    }
    if (tid < 96) sbias[tid] = bhh[(tid >> 5) * 512 + ng * 32 + (tid & 31)];

    // zero owned region of initial state
    if (tid < 128) {
        int b = mg * 16 + (tid >> 3);
        int cc = ng * 32 + (tid & 7) * 4;
        uint2 zb = {0u, 0u};
        *(uint2*)&g_hbhi[0][b * 512 + cc] = zb;
        *(uint2*)&g_hblo[0][b * 512 + cc] = zb;
    }
    __syncthreads();

    const int a_r  = (lane & 7) + ((lane >> 3) & 1) * 8;
    const int a_co = lane >> 4;
    const int b_r  = lane & 7;
    const int b_co = (lane >> 3) & 1;
    const int b_m  = lane >> 3;
    const uint32_t AbHi = sb + A_HI + a_r * 1024;
    const uint32_t AbLo = sb + A_LO + a_r * 1024;
    uint32_t BbHi[3], BbLo[3];
#pragma unroll
    for (int f = 0; f < 3; f++) {
        int n = f * 32 + nq * 8 + b_r;             // gate f, col block nq*8
        BbHi[f] = sb + W_HI + n * 1024;
        BbLo[f] = sb + W_LO + n * 1024;
    }

    // hoist W-hi fragments into registers
    uint32_t bhr[3][16][2];
#pragma unroll
    for (int kk0 = 0; kk0 < 16; kk0++) {
        int kk = kh * 16 + kk0;
        uint32_t bsw = (uint32_t)(((2 * kk + b_co) ^ (b_r & 7)) << 4);
#pragma unroll
        for (int f = 0; f < 3; f++)
            LDSM2(bhr[f][kk0], BbHi[f] + bsw);
    }
    __syncthreads();    // hoist reads done before dred may overlay W_HI

    if (tid == 0) relstore(&g_flag[mg][ng][0], base + 1);

    // staging: thread stages chunk cc = half*32 + (tid&31)
    unsigned* myflag = &g_flag[mg][(half * 32 + (tid & 31)) >> 2][0];

    // fragment epilogue mapping (kh==0 warps only)
    const int ebr  = lane >> 2;                    // row 0..7 (and +8)
    const int ehc  = nq * 8 + (lane & 3) * 2;      // col within 32 (even)
    const int bgA  = mg * 16 + ebr;
    const int bgB  = bgA + 8;
    const int hcg  = ng * 32 + ehc;                // global h col
    const float* xpA = xp + (size_t)bgA * TT * GG + hcg;
    const float* xpB = xp + (size_t)bgB * TT * GG + hcg;
    const int pslot = (nq * 32 + lane) * 13;       // pad stride 13: conflict-free

    for (int t = 0; t < TT; t++) {
        const int cur = t & 1, nxt = cur ^ 1;
        float* dd = dred + (t & 1) * 1664;         // parity buffer (128*13)

        // kh0: prefetch xp + hold (fragment layout) before the flag wait
        float xr0x, xr0y, xr1x, xr1y, xz0x, xz0y, xz1x, xz1y, xn0x, xn0y, xn1x, xn1y;
        float hoA0, hoA1, hoB0, hoB1;
        if (kh == 0) {
            const size_t to = (size_t)t * GG;
            float2 v;
            v = *(const float2*)(xpA + to);         xr0x = v.x; xr0y = v.y;
            v = *(const float2*)(xpA + to + 512);   xz0x = v.x; xz0y = v.y;
            v = *(const float2*)(xpA + to + 1024);  xn0x = v.x; xn0y = v.y;
            v = *(const float2*)(xpB + to);         xr1x = v.x; xr1y = v.y;
            v = *(const float2*)(xpB + to + 512);   xz1x = v.x; xz1y = v.y;
            v = *(const float2*)(xpB + to + 1024);  xn1x = v.x; xn1y = v.y;
            __nv_bfloat162 h2, l2;
            h2 = *(const __nv_bfloat162*)&g_hbhi[cur][bgA * 512 + hcg];
            l2 = *(const __nv_bfloat162*)&g_hblo[cur][bgA * 512 + hcg];
            hoA0 = __bfloat162float(h2.x) + __bfloat162float(l2.x);
            hoA1 = __bfloat162float(h2.y) + __bfloat162float(l2.y);
            h2 = *(const __nv_bfloat162*)&g_hbhi[cur][bgB * 512 + hcg];
            l2 = *(const __nv_bfloat162*)&g_hblo[cur][bgB * 512 + hcg];
            hoB0 = __bfloat162float(h2.x) + __bfloat162float(l2.x);
            hoB1 = __bfloat162float(h2.y) + __bfloat162float(l2.y);
        }

        // per-thread wait for the single producer of this thread's chunks
        {
            const unsigned tgt = base + 1 + (unsigned)t;
            while ((int)(acqload(myflag) - tgt) < 0) { }
        }

        // stage own K-half of the h tile
        const __nv_bfloat16* hh = &g_hbhi[cur][(size_t)mg * 16 * 512];
        const __nv_bfloat16* hl = &g_hblo[cur][(size_t)mg * 16 * 512];
#pragma unroll
        for (int j = 0; j < 4; j++) {
            int idx = (tid & 127) + j * 128;
            int r = idx >> 5;
            int cc = half * 32 + (idx & 31);
            uint32_t off = (uint32_t)(r * 1024 + ((cc ^ (r & 7)) << 4));
            CP16(sb + A_HI + off, hh + r * 512 + cc * 8);
            CP16(sb + A_LO + off, hl + r * 512 + cc * 8);
        }
        CPCOMMIT(); CPWAIT0();
        asm volatile("bar.sync %0, 128;" :: "r"(1 + half) : "memory");

        float acc[3][4];
#pragma unroll
        for (int f = 0; f < 3; f++)
#pragma unroll
            for (int q = 0; q < 4; q++) acc[f][q] = 0.f;

#pragma unroll
        for (int kp = 0; kp < 8; kp++) {
            int kk = kh * 16 + kp * 2;
            uint32_t asw0 = (uint32_t)(((2 * kk + a_co) ^ (a_r & 7)) << 4);
            uint32_t asw1 = (uint32_t)(((2 * kk + 2 + a_co) ^ (a_r & 7)) << 4);
            uint32_t ahi0[4], alo0[4], ahi1[4], alo1[4];
            LDSM4(ahi0, AbHi + asw0);
            LDSM4(alo0, AbLo + asw0);
            LDSM4(ahi1, AbHi + asw1);
            LDSM4(alo1, AbLo + asw1);
            uint32_t bsw = (uint32_t)(((2 * kk + b_m) ^ (b_r & 7)) << 4);
#pragma unroll
            for (int f = 0; f < 3; f++) {
                uint32_t bl[4];
                LDSM4(bl, BbLo[f] + bsw);
                MMA16816(acc[f], ahi0, bhr[f][kp * 2]);
                MMA16816(acc[f], alo0, bhr[f][kp * 2]);
                MMA16816(acc[f], ahi0, bl);
                MMA16816(acc[f], ahi1, bhr[f][kp * 2 + 1]);
                MMA16816(acc[f], alo1, bhr[f][kp * 2 + 1]);
                MMA16816(acc[f], ahi1, bl + 2);
            }
        }

        if (kh == 1) {
            // dump partials for the partner warp; then run ahead to t+1
            float* pr = dd + pslot;
#pragma unroll
            for (int f = 0; f < 3; f++) {
                pr[f * 4 + 0] = acc[f][0]; pr[f * 4 + 1] = acc[f][1];
                pr[f * 4 + 2] = acc[f][2]; pr[f * 4 + 3] = acc[f][3];
            }
            asm volatile("bar.sync %0, 64;" :: "r"(8 + nq) : "memory");
        } else {
            asm volatile("bar.sync %0, 64;" :: "r"(8 + nq) : "memory");
            const float* pr = dd + pslot;
            float D[3][4];
#pragma unroll
            for (int f = 0; f < 3; f++) {
#pragma unroll
                for (int q = 0; q < 4; q++) D[f][q] = acc[f][q] + pr[f * 4 + q];
            }
            float bR0 = sbias[ehc],      bR1 = sbias[ehc + 1];
            float bZ0 = sbias[32 + ehc], bZ1 = sbias[32 + ehc + 1];
            float bN0 = sbias[64 + ehc], bN1 = sbias[64 + ehc + 1];

            // elements: q=0 (rowA,col0) q=1 (rowA,col1) q=2 (rowB,col0) q=3 (rowB,col1)
            float xrv[4] = { xr0x, xr0y, xr1x, xr1y };
            float xzv[4] = { xz0x, xz0y, xz1x, xz1y };
            float xnv[4] = { xn0x, xn0y, xn1x, xn1y };
            float hov[4] = { hoA0, hoA1, hoB0, hoB1 };
            float bRv[4] = { bR0, bR1, bR0, bR1 };
            float bZv[4] = { bZ0, bZ1, bZ0, bZ1 };
            float bNv[4] = { bN0, bN1, bN0, bN1 };

            __nv_bfloat16 hb[4], lb[4];
#pragma unroll
            for (int q = 0; q < 4; q++) {
                float r = __fdividef(1.f, 1.f + __expf(-(xrv[q] + D[0][q] + bRv[q])));
                float z = __fdividef(1.f, 1.f + __expf(-(xzv[q] + D[1][q] + bZv[q])));
                float pre = xnv[q] + r * (D[2][q] + bNv[q]);
                float e2 = __expf(2.f * pre);
                float n = 1.f - __fdividef(2.f, e2 + 1.f);
                float hv = (1.f - z) * n + z * hov[q];
                hb[q] = __float2bfloat16(hv);
                lb[q] = __float2bfloat16(hv - __bfloat162float(hb[q]));
            }
            // paired-column stores (cols hcg, hcg+1)
            *(__nv_bfloat162*)&g_hbhi[nxt][bgA * 512 + hcg] = __nv_bfloat162(hb[0], hb[1]);
            *(__nv_bfloat162*)&g_hblo[nxt][bgA * 512 + hcg] = __nv_bfloat162(lb[0], lb[1]);
            *(__nv_bfloat162*)&g_hbhi[nxt][bgB * 512 + hcg] = __nv_bfloat162(hb[2], hb[3]);
            *(__nv_bfloat162*)&g_hblo[nxt][bgB * 512 + hcg] = __nv_bfloat162(lb[2], lb[3]);

            asm volatile("bar.sync 7, 128;" ::: "memory");
            if (tid == 0) relstore(&g_flag[mg][ng][0], base + 2 + (unsigned)t);

            if (seqhi) {    // history off the critical path
                size_t soA = ((size_t)bgA * TT + t) * HH + hcg;
                size_t soB = ((size_t)bgB * TT + t) * HH + hcg;
                *(__nv_bfloat162*)&seqhi[soA] = __nv_bfloat162(hb[0], hb[1]);
                *(__nv_bfloat162*)&seqlo[soA] = __nv_bfloat162(lb[0], lb[1]);
                *(__nv_bfloat162*)&seqhi[soB] = __nv_bfloat162(hb[2], hb[3]);
                *(__nv_bfloat162*)&seqlo[soB] = __nv_bfloat162(lb[2], lb[3]);
            }
        }
    }
}

// ---------------- final linear ----------------
__global__ void final_linear(const float* __restrict__ Wl, const float* __restrict__ bl,
                             float* __restrict__ out)
{
    __shared__ float ssum[4];
    int b = blockIdx.x, tid = threadIdx.x;
    float s = 0.f;
    for (int k = tid; k < 512; k += 128) {
        float hv = __bfloat162float(g_hbhi[0][b * 512 + k])
                 + __bfloat162float(g_hblo[0][b * 512 + k]);
        s += hv * Wl[k];
    }
#pragma unroll
    for (int o = 16; o > 0; o >>= 1) s += __shfl_down_sync(0xffffffffu, s, o);
    if ((tid & 31) == 0) ssum[tid >> 5] = s;
    __syncthreads();
    if (tid == 0) out[b] = ssum[0] + ssum[1] + ssum[2] + ssum[3] + bl[0];
}

// ---------------- launch ----------------
extern "C" void kernel_launch(void* const* d_in, const int* in_sizes, int n_in,
                              void* d_out, int out_size)
{
    const float* x    = (const float*)d_in[0];
    const float* Wih0 = (const float*)d_in[1];
    const float* Whh0 = (const float*)d_in[2];
    const float* bih0 = (const float*)d_in[3];
    const float* bhh0 = (const float*)d_in[4];
    const float* Wih1 = (const float*)d_in[5];
    const float* Whh1 = (const float*)d_in[6];
    const float* bih1 = (const float*)d_in[7];
    const float* bhh1 = (const float*)d_in[8];
    const float* Wlin = (const float*)d_in[9];
    const float* blin = (const float*)d_in[10];
    float* out = (float*)d_out;

    float* xp;
    __nv_bfloat16 *xhi, *xlo, *h1hi, *h1lo, *w0hi, *w0lo, *w1hi, *w1lo, *whhhi, *whhlo;
    cudaGetSymbolAddress((void**)&xp, g_xp);
    cudaGetSymbolAddress((void**)&xhi, g_xhi);
    cudaGetSymbolAddress((void**)&xlo, g_xlo);
    cudaGetSymbolAddress((void**)&h1hi, g_h1hi);
    cudaGetSymbolAddress((void**)&h1lo, g_h1lo);
    cudaGetSymbolAddress((void**)&w0hi, g_w0hi);
    cudaGetSymbolAddress((void**)&w0lo, g_w0lo);
    cudaGetSymbolAddress((void**)&w1hi, g_w1hi);
    cudaGetSymbolAddress((void**)&w1lo, g_w1lo);
    cudaGetSymbolAddress((void**)&whhhi, g_whhhi);
    cudaGetSymbolAddress((void**)&whhlo, g_whhlo);
    const size_t WHH_SZ = 16 * 96 * 512;

    const int GEMM_SMEM = 3 * 65536;
    const int GRU_SMEM  = 512 + 2 * 98304 + 2 * 16384;
    cudaFuncSetAttribute(gemm_mma<256>, cudaFuncAttributeMaxDynamicSharedMemorySize, GEMM_SMEM);
    cudaFuncSetAttribute(gemm_mma<512>, cudaFuncAttributeMaxDynamicSharedMemorySize, GEMM_SMEM);
    cudaFuncSetAttribute(gru_mma, cudaFuncAttributeMaxDynamicSharedMemorySize, GRU_SMEM);

    {
        size_t n = (size_t)BB * TT * 256;
        split_f32<<<(unsigned)((n + 255) / 256), 256>>>(x, n, xhi, xlo);
    }
    split_f32<<<(GG * 256 + 255) / 256, 256>>>(Wih0, (size_t)GG * 256, w0hi, w0lo);
    split_f32<<<(GG * 512 + 255) / 256, 256>>>(Wih1, (size_t)GG * 512, w1hi, w1lo);
    split_whh<<<3072, 256>>>(Whh0, whhhi, whhlo);
    split_whh<<<3072, 256>>>(Whh1, whhhi + WHH_SZ, whhlo + WHH_SZ);

    dim3 gg(GG / 128, (BB * TT) / 128);

    gemm_mma<256><<<gg, 256, GEMM_SMEM>>>(xhi, xlo, w0hi, w0lo, bih0, xp);
    gru_mma<<<NCTA, 256, GRU_SMEM>>>(xp, whhhi, whhlo, bhh0, h1hi, h1lo);
    gemm_mma<512><<<gg, 256, GEMM_SMEM>>>(h1hi, h1lo, w1hi, w1lo, bih1, xp);
    gru_mma<<<NCTA, 256, GRU_SMEM>>>(xp, whhhi + WHH_SZ, whhlo + WHH_SZ, bhh1, nullptr, nullptr);
    final_linear<<<BB, 128>>>(Wlin, blin, out);
}

// round 13
// speedup vs baseline: 1.5823x; 1.5823x over previous
#include <cuda_runtime.h>
#include <cuda_bf16.h>
#include <math.h>
#include <stdint.h>

#define BB 128
#define TT 1024
#define HH 512
#define GG 1536
#define NCTA 128

// ---------------- device scratch (no allocation) ----------------
__device__ float g_xp[(size_t)BB * TT * GG];
__device__ __nv_bfloat16 g_xhi[(size_t)BB * TT * 256];
__device__ __nv_bfloat16 g_xlo[(size_t)BB * TT * 256];
__device__ __nv_bfloat16 g_h1hi[(size_t)BB * TT * HH];
__device__ __nv_bfloat16 g_h1lo[(size_t)BB * TT * HH];
__device__ __nv_bfloat16 g_w0hi[GG * 256], g_w0lo[GG * 256];
__device__ __nv_bfloat16 g_w1hi[GG * HH],  g_w1lo[GG * HH];
__device__ __nv_bfloat16 g_whhhi[2][16 * 96 * 512];
__device__ __nv_bfloat16 g_whhlo[2][16 * 96 * 512];
__device__ __nv_bfloat16 g_hbhi[2][BB * HH];
__device__ __nv_bfloat16 g_hblo[2][BB * HH];
// per-CTA progress flags: [mg][ng][pad 128B]; monotonic across launches/replays
__device__ unsigned g_flag[8][16][32];

// ---------------- PTX helpers (baseline PTX only) ----------------
__device__ __forceinline__ uint32_t smem_u32(const void* p) {
    uint32_t a;
    asm("{ .reg .u64 t; cvta.to.shared.u64 t, %1; cvt.u32.u64 %0, t; }" : "=r"(a) : "l"(p));
    return a;
}

#define CP16(dst, src) \
    asm volatile("cp.async.cg.shared.global [%0], [%1], 16;" :: "r"(dst), "l"(src))
#define CPCOMMIT() asm volatile("cp.async.commit_group;")
#define CPWAIT0()  asm volatile("cp.async.wait_group 0;")
#define CPWAIT1()  asm volatile("cp.async.wait_group 1;")

#define LDSM4(r, a) \
    asm volatile("ldmatrix.sync.aligned.m8n8.x4.shared.b16 {%0,%1,%2,%3}, [%4];" \
        : "=r"((r)[0]), "=r"((r)[1]), "=r"((r)[2]), "=r"((r)[3]) : "r"(a))
#define LDSM2(r, a) \
    asm volatile("ldmatrix.sync.aligned.m8n8.x2.shared.b16 {%0,%1}, [%2];" \
        : "=r"((r)[0]), "=r"((r)[1]) : "r"(a))

#define MMA16816(c, a, b) \
    asm volatile("mma.sync.aligned.m16n8k16.row.col.f32.bf16.bf16.f32 " \
        "{%0,%1,%2,%3}, {%4,%5,%6,%7}, {%8,%9}, {%0,%1,%2,%3};" \
        : "+f"((c)[0]), "+f"((c)[1]), "+f"((c)[2]), "+f"((c)[3]) \
        : "r"((a)[0]), "r"((a)[1]), "r"((a)[2]), "r"((a)[3]), "r"((b)[0]), "r"((b)[1]))

__device__ __forceinline__ void relstore(unsigned* p, unsigned v) {
    asm volatile("st.release.gpu.u32 [%0], %1;" :: "l"(p), "r"(v) : "memory");
}
__device__ __forceinline__ unsigned acqload(unsigned* p) {
    unsigned v;
    asm volatile("ld.acquire.gpu.u32 %0, [%1];" : "=r"(v) : "l"(p) : "memory");
    return v;
}

// ---------------- conversions ----------------
__global__ void split_f32(const float* __restrict__ src, size_t n,
                          __nv_bfloat16* __restrict__ hi, __nv_bfloat16* __restrict__ lo) {
    size_t i = (size_t)blockIdx.x * blockDim.x + threadIdx.x;
    if (i < n) {
        float v = src[i];
        __nv_bfloat16 h = __float2bfloat16(v);
        hi[i] = h;
        lo[i] = __float2bfloat16(v - __bfloat162float(h));
    }
}

// reorder Whh [1536,512] -> [16 ng][96][512]
__global__ void split_whh(const float* __restrict__ W,
                          __nv_bfloat16* __restrict__ hi, __nv_bfloat16* __restrict__ lo) {
    int i = blockIdx.x * 256 + threadIdx.x;
    int k = i & 511;
    int ro = i >> 9;
    int ng = ro / 96, j = ro % 96;
    int g = j >> 5, jj = j & 31;
    float v = W[(size_t)(g * 512 + ng * 32 + jj) * 512 + k];
    __nv_bfloat16 h = __float2bfloat16(v);
    hi[i] = h;
    lo[i] = __float2bfloat16(v - __bfloat162float(h));
}

// ---------------- mma.sync GEMM, 3-stage cp.async pipeline (round-9 config) ----------------
template <int K>
__global__ void __launch_bounds__(256) gemm_mma(
    const __nv_bfloat16* __restrict__ Ahi, const __nv_bfloat16* __restrict__ Alo,
    const __nv_bfloat16* __restrict__ Bhi, const __nv_bfloat16* __restrict__ Blo,
    const float* __restrict__ bias, float* __restrict__ C)
{
    extern __shared__ char smx[];
    const uint32_t sb = smem_u32(smx);
    const int tid = threadIdx.x, w = tid >> 5, lane = tid & 31;
    const int wm = w >> 2, wn = w & 3;
    const int m0 = blockIdx.y * 128, n0 = blockIdx.x * 128;

    float c[4][4][4];
#pragma unroll
    for (int i = 0; i < 4; i++)
#pragma unroll
        for (int j = 0; j < 4; j++)
#pragma unroll
            for (int q = 0; q < 4; q++) c[i][j][q] = 0.f;

    const int a_r  = (lane & 7) + ((lane >> 3) & 1) * 8;
    const int a_co = lane >> 4;
    const int b_r  = lane & 7;
    const int b_co = (lane >> 3) & 1;

    const int KC = K / 64;
    const int NIT = 3 * KC;

    auto stage = [&](int it, int buf) {
        int p = it / KC;
        int kc = (it - p * KC) * 64;
        const __nv_bfloat16* Ap = (p == 1) ? Alo : Ahi;
        const __nv_bfloat16* Bp = (p == 2) ? Blo : Bhi;
#pragma unroll
        for (int j = 0; j < 4; j++) {
            int idx = tid + j * 256;
            int r = idx >> 3, cc = idx & 7;
            uint32_t off = (uint32_t)(r * 128 + ((cc ^ (r & 7)) << 4));
            CP16(sb + buf * 32768 + off, Ap + (size_t)(m0 + r) * K + kc + cc * 8);
            CP16(sb + buf * 32768 + 16384 + off, Bp + (size_t)(n0 + r) * K + kc + cc * 8);
        }
    };

    stage(0, 0); CPCOMMIT();
    stage(1, 1); CPCOMMIT();
    for (int it = 0; it < NIT; it++) {
        int buf = it % 3;
        CPWAIT1();
        __syncthreads();

        const uint32_t Ab = sb + buf * 32768 + (wm * 64) * 128;
        const uint32_t Bb = sb + buf * 32768 + 16384 + (wn * 32) * 128;
#pragma unroll
        for (int kk = 0; kk < 4; kk++) {
            uint32_t a[4][4];
            uint32_t asw = (uint32_t)(((2 * kk + a_co) ^ (a_r & 7)) << 4);
#pragma unroll
            for (int mt = 0; mt < 4; mt++)
                LDSM4(a[mt], Ab + (mt * 16 + a_r) * 128 + asw);
            uint32_t bsw = (uint32_t)(((2 * kk + b_co) ^ (b_r & 7)) << 4);
#pragma unroll
            for (int nt = 0; nt < 4; nt++) {
                uint32_t b[2];
                LDSM2(b, Bb + (nt * 8 + b_r) * 128 + bsw);
#pragma unroll
                for (int mt = 0; mt < 4; mt++)
                    MMA16816(c[mt][nt], a[mt], b);
            }
        }
        if (it + 2 < NIT) stage(it + 2, (it + 2) % 3);
        CPCOMMIT();
    }

#pragma unroll
    for (int nt = 0; nt < 4; nt++) {
        int col = n0 + wn * 32 + nt * 8 + (lane & 3) * 2;
        float2 bv = *(const float2*)&bias[col];
#pragma unroll
        for (int mt = 0; mt < 4; mt++) {
            int row = m0 + wm * 64 + mt * 16 + (lane >> 2);
            float2 v0 = { c[mt][nt][0] + bv.x, c[mt][nt][1] + bv.y };
            float2 v1 = { c[mt][nt][2] + bv.x, c[mt][nt][3] + bv.y };
            *(float2*)&C[(size_t)row * GG + col] = v0;
            *(float2*)&C[(size_t)(row + 8) * GG + col] = v1;
        }
    }
}

// ---------------- persistent mma.sync GRU layer (round-9 form + arrive/sync release) ----------------
__global__ void __launch_bounds__(256, 1) gru_mma(
    const float* __restrict__ xp,
    const __nv_bfloat16* __restrict__ Whi_g, const __nv_bfloat16* __restrict__ Wlo_g,
    const float* __restrict__ bhh,
    __nv_bfloat16* __restrict__ seqhi, __nv_bfloat16* __restrict__ seqlo)
{
    extern __shared__ char smx[];
    const uint32_t sb = smem_u32(smx);
    float* sbias = (float*)smx;                    // 96 floats
    const uint32_t W_HI = 512;
    const uint32_t W_LO = 512 + 98304;
    const uint32_t A_HI = 512 + 196608;
    const uint32_t A_LO = A_HI + 16384;
    float* dred = (float*)(smx + W_HI);            // overlays W_HI (dead after hoist)

    const int tid = threadIdx.x, w = tid >> 5, lane = tid & 31;
    const int nq = w & 3, kh = w >> 2;
    const int half = tid >> 7;                     // == kh for this warp layout
    const int ng = blockIdx.x & 15, mg = blockIdx.x >> 4;

    const unsigned base = g_flag[mg][ng][0];       // stable between launches

    // persistent W slice, swizzled
    const __nv_bfloat16* wh = Whi_g + (size_t)ng * 96 * 512;
    const __nv_bfloat16* wl = Wlo_g + (size_t)ng * 96 * 512;
    for (int idx = tid; idx < 6144; idx += 256) {
        int r = idx >> 6, cc = idx & 63;
        uint32_t off = (uint32_t)(r * 1024 + ((cc ^ (r & 7)) << 4));
        *(uint4*)(smx + W_HI + off) = *(const uint4*)(wh + r * 512 + cc * 8);
        *(uint4*)(smx + W_LO + off) = *(const uint4*)(wl + r * 512 + cc * 8);
    }
    if (tid < 96) sbias[tid] = bhh[(tid >> 5) * 512 + ng * 32 + (tid & 31)];

    // zero owned region of initial state
    if (tid < 128) {
        int b = mg * 16 + (tid >> 3);
        int cc = ng * 32 + (tid & 7) * 4;
        uint2 zb = {0u, 0u};
        *(uint2*)&g_hbhi[0][b * 512 + cc] = zb;
        *(uint2*)&g_hblo[0][b * 512 + cc] = zb;
    }
    __syncthreads();

    const int a_r  = (lane & 7) + ((lane >> 3) & 1) * 8;
    const int a_co = lane >> 4;
    const int b_r  = lane & 7;
    const int b_co = (lane >> 3) & 1;
    const int b_m  = lane >> 3;                    // 0..3: K-chunk within .x4 fetch
    const uint32_t AbHi = sb + A_HI + a_r * 1024;
    const uint32_t AbLo = sb + A_LO + a_r * 1024;
    uint32_t BbHi[3], BbLo[3];
#pragma unroll
    for (int f = 0; f < 3; f++) {
        int n = nq * 24 + f * 8 + b_r;
        BbHi[f] = sb + W_HI + n * 1024;
        BbLo[f] = sb + W_LO + n * 1024;
    }

    // hoist W-hi fragments into registers (loop-invariant over all 1024 steps)
    uint32_t bhr[3][16][2];
#pragma unroll
    for (int kk0 = 0; kk0 < 16; kk0++) {
        int kk = kh * 16 + kk0;
        uint32_t bsw = (uint32_t)(((2 * kk + b_co) ^ (b_r & 7)) << 4);
#pragma unroll
        for (int f = 0; f < 3; f++)
            LDSM2(bhr[f][kk0], BbHi[f] + bsw);
    }
    __syncthreads();    // hoist reads of W_HI done before dred may overlay it

    // init-done flag (release: makes zero-init visible to group)
    if (tid == 0) relstore(&g_flag[mg][ng][0], base + 1);

    // staging mapping: thread stages chunk cc = half*32 + (tid&31), rows via j
    unsigned* myflag = &g_flag[mg][(half * 32 + (tid & 31)) >> 2][0];

    // epilogue/prefetch thread mapping
    const int b0  = tid >> 5;
    const int cc0 = tid & 31;
    const int bg0 = mg * 16 + b0;
    const int bg1 = bg0 + 8;
    const int hc0 = ng * 32 + cc0;
    const float* xpp0 = xp + (size_t)bg0 * TT * GG + hc0;
    const float* xpp1 = xp + (size_t)bg1 * TT * GG + hc0;

    for (int t = 0; t < TT; t++) {
        const int cur = t & 1, nxt = cur ^ 1;

        // prefetch xp + own hold (no inter-CTA dependency) before the flag wait
        const size_t to = (size_t)t * GG;
        float pxr0 = __ldg(xpp0 + to),        pxr1 = __ldg(xpp1 + to);
        float pxz0 = __ldg(xpp0 + to + 512),  pxz1 = __ldg(xpp1 + to + 512);
        float pxn0 = __ldg(xpp0 + to + 1024), pxn1 = __ldg(xpp1 + to + 1024);
        float phold0 = __bfloat162float(g_hbhi[cur][bg0 * 512 + hc0])
                     + __bfloat162float(g_hblo[cur][bg0 * 512 + hc0]);
        float phold1 = __bfloat162float(g_hbhi[cur][bg1 * 512 + hc0])
                     + __bfloat162float(g_hblo[cur][bg1 * 512 + hc0]);

        // per-thread wait for the single producer of this thread's chunks
        {
            const unsigned tgt = base + 1 + (unsigned)t;
            while ((int)(acqload(myflag) - tgt) < 0) { }
        }

        // stage own K-half of the h tile (16 rows x 256 cols, hi+lo)
        const __nv_bfloat16* hh = &g_hbhi[cur][(size_t)mg * 16 * 512];
        const __nv_bfloat16* hl = &g_hblo[cur][(size_t)mg * 16 * 512];
#pragma unroll
        for (int j = 0; j < 4; j++) {
            int idx = (tid & 127) + j * 128;
            int r = idx >> 5;                     // 0..15
            int cc = half * 32 + (idx & 31);      // own half's chunk
            uint32_t off = (uint32_t)(r * 1024 + ((cc ^ (r & 7)) << 4));
            CP16(sb + A_HI + off, hh + r * 512 + cc * 8);
            CP16(sb + A_LO + off, hl + r * 512 + cc * 8);
        }
        CPCOMMIT(); CPWAIT0();
        asm volatile("bar.sync %0, 128;" :: "r"(1 + half) : "memory");

        float acc[3][4];
#pragma unroll
        for (int f = 0; f < 3; f++)
#pragma unroll
            for (int q = 0; q < 4; q++) acc[f][q] = 0.f;

#pragma unroll
        for (int kp = 0; kp < 8; kp++) {
            int kk = kh * 16 + kp * 2;            // two K-steps per iter
            uint32_t asw0 = (uint32_t)(((2 * kk + a_co) ^ (a_r & 7)) << 4);
            uint32_t asw1 = (uint32_t)(((2 * kk + 2 + a_co) ^ (a_r & 7)) << 4);
            uint32_t ahi0[4], alo0[4], ahi1[4], alo1[4];
            LDSM4(ahi0, AbHi + asw0);
            LDSM4(alo0, AbLo + asw0);
            LDSM4(ahi1, AbHi + asw1);
            LDSM4(alo1, AbLo + asw1);
            uint32_t bsw = (uint32_t)(((2 * kk + b_m) ^ (b_r & 7)) << 4);
#pragma unroll
            for (int f = 0; f < 3; f++) {
                uint32_t bl[4];
                LDSM4(bl, BbLo[f] + bsw);         // covers kk and kk+1
                MMA16816(acc[f], ahi0, bhr[f][kp * 2]);
                MMA16816(acc[f], alo0, bhr[f][kp * 2]);
                MMA16816(acc[f], ahi0, bl);
                MMA16816(acc[f], ahi1, bhr[f][kp * 2 + 1]);
                MMA16816(acc[f], alo1, bhr[f][kp * 2 + 1]);
                MMA16816(acc[f], ahi1, bl + 2);
            }
        }
        // no sync needed: dred (W_HI region) is disjoint from A/W_LO LDSM reads

#pragma unroll
        for (int f = 0; f < 3; f++) {
            int colc = nq * 24 + f * 8 + (lane & 3) * 2;
            int br = lane >> 2;
            float* p0 = &dred[(kh * 16 + br) * 100 + colc];
            float* p1 = &dred[(kh * 16 + br + 8) * 100 + colc];
            p0[0] = acc[f][0]; p0[1] = acc[f][1];
            p1[0] = acc[f][2]; p1[1] = acc[f][3];
        }
        __syncthreads();

        // fused gate epilogue; keep results in regs, write state, release, then seq
        __nv_bfloat16 rhb[2], rlb[2];
#pragma unroll
        for (int pp = 0; pp < 2; pp++) {
            int b = b0 + pp * 8;
            float Dr = dred[b * 100 + cc0]      + dred[(16 + b) * 100 + cc0];
            float Dz = dred[b * 100 + 32 + cc0] + dred[(16 + b) * 100 + 32 + cc0];
            float Dn = dred[b * 100 + 64 + cc0] + dred[(16 + b) * 100 + 64 + cc0];
            float xr = pp ? pxr1 : pxr0;
            float xz = pp ? pxz1 : pxz0;
            float xn = pp ? pxn1 : pxn0;
            float hold = pp ? phold1 : phold0;
            int bg = pp ? bg1 : bg0;
            float r = __fdividef(1.f, 1.f + __expf(-(xr + Dr + sbias[cc0])));
            float z = __fdividef(1.f, 1.f + __expf(-(xz + Dz + sbias[32 + cc0])));
            float pre = xn + r * (Dn + sbias[64 + cc0]);
            float e2 = __expf(2.f * pre);
            float n = 1.f - __fdividef(2.f, e2 + 1.f);
            float hv = (1.f - z) * n + z * hold;
            __nv_bfloat16 hb = __float2bfloat16(hv);
            float lo = hv - __bfloat162float(hb);
            __nv_bfloat16 lb = __float2bfloat16(lo);
            g_hbhi[nxt][bg * 512 + hc0] = hb;
            g_hblo[nxt][bg * 512 + hc0] = lb;
            rhb[pp] = hb; rlb[pp] = lb;
        }
        // release barrier split: producers arrive (non-blocking) and run ahead
        // into t+1 prefetch/poll/staging; warp 0 syncs then publishes the flag.
        if (w == 0) {
            asm volatile("bar.sync 6, 256;" ::: "memory");
            if (tid == 0) relstore(&g_flag[mg][ng][0], base + 2 + (unsigned)t);
        } else {
            asm volatile("bar.arrive 6, 256;" ::: "memory");
        }

        if (seqhi) {        // history writes off the critical path
#pragma unroll
            for (int pp = 0; pp < 2; pp++) {
                int bg = pp ? bg1 : bg0;
                size_t so = ((size_t)bg * TT + t) * HH + hc0;
                seqhi[so] = rhb[pp];
                seqlo[so] = rlb[pp];
            }
        }
    }
}

// ---------------- final linear ----------------
__global__ void final_linear(const float* __restrict__ Wl, const float* __restrict__ bl,
                             float* __restrict__ out)
{
    __shared__ float ssum[4];
    int b = blockIdx.x, tid = threadIdx.x;
    float s = 0.f;
    for (int k = tid; k < 512; k += 128) {
        float hv = __bfloat162float(g_hbhi[0][b * 512 + k])
                 + __bfloat162float(g_hblo[0][b * 512 + k]);
        s += hv * Wl[k];
    }
#pragma unroll
    for (int o = 16; o > 0; o >>= 1) s += __shfl_down_sync(0xffffffffu, s, o);
    if ((tid & 31) == 0) ssum[tid >> 5] = s;
    __syncthreads();
    if (tid == 0) out[b] = ssum[0] + ssum[1] + ssum[2] + ssum[3] + bl[0];
}

// ---------------- launch ----------------
extern "C" void kernel_launch(void* const* d_in, const int* in_sizes, int n_in,
                              void* d_out, int out_size)
{
    const float* x    = (const float*)d_in[0];
    const float* Wih0 = (const float*)d_in[1];
    const float* Whh0 = (const float*)d_in[2];
    const float* bih0 = (const float*)d_in[3];
    const float* bhh0 = (const float*)d_in[4];
    const float* Wih1 = (const float*)d_in[5];
    const float* Whh1 = (const float*)d_in[6];
    const float* bih1 = (const float*)d_in[7];
    const float* bhh1 = (const float*)d_in[8];
    const float* Wlin = (const float*)d_in[9];
    const float* blin = (const float*)d_in[10];
    float* out = (float*)d_out;

    float* xp;
    __nv_bfloat16 *xhi, *xlo, *h1hi, *h1lo, *w0hi, *w0lo, *w1hi, *w1lo, *whhhi, *whhlo;
    cudaGetSymbolAddress((void**)&xp, g_xp);
    cudaGetSymbolAddress((void**)&xhi, g_xhi);
    cudaGetSymbolAddress((void**)&xlo, g_xlo);
    cudaGetSymbolAddress((void**)&h1hi, g_h1hi);
    cudaGetSymbolAddress((void**)&h1lo, g_h1lo);
    cudaGetSymbolAddress((void**)&w0hi, g_w0hi);
    cudaGetSymbolAddress((void**)&w0lo, g_w0lo);
    cudaGetSymbolAddress((void**)&w1hi, g_w1hi);
    cudaGetSymbolAddress((void**)&w1lo, g_w1lo);
    cudaGetSymbolAddress((void**)&whhhi, g_whhhi);
    cudaGetSymbolAddress((void**)&whhlo, g_whhlo);
    const size_t WHH_SZ = 16 * 96 * 512;

    const int GEMM_SMEM = 3 * 32768;
    const int GRU_SMEM  = 512 + 2 * 98304 + 2 * 16384;
    cudaFuncSetAttribute(gemm_mma<256>, cudaFuncAttributeMaxDynamicSharedMemorySize, GEMM_SMEM);
    cudaFuncSetAttribute(gemm_mma<512>, cudaFuncAttributeMaxDynamicSharedMemorySize, GEMM_SMEM);
    cudaFuncSetAttribute(gru_mma, cudaFuncAttributeMaxDynamicSharedMemorySize, GRU_SMEM);

    {
        size_t n = (size_t)BB * TT * 256;
        split_f32<<<(unsigned)((n + 255) / 256), 256>>>(x, n, xhi, xlo);
    }
    split_f32<<<(GG * 256 + 255) / 256, 256>>>(Wih0, (size_t)GG * 256, w0hi, w0lo);
    split_f32<<<(GG * 512 + 255) / 256, 256>>>(Wih1, (size_t)GG * 512, w1hi, w1lo);
    split_whh<<<3072, 256>>>(Whh0, whhhi, whhlo);
    split_whh<<<3072, 256>>>(Whh1, whhhi + WHH_SZ, whhlo + WHH_SZ);

    dim3 gg(GG / 128, (BB * TT) / 128);

    gemm_mma<256><<<gg, 256, GEMM_SMEM>>>(xhi, xlo, w0hi, w0lo, bih0, xp);
    gru_mma<<<NCTA, 256, GRU_SMEM>>>(xp, whhhi, whhlo, bhh0, h1hi, h1lo);
    gemm_mma<512><<<gg, 256, GEMM_SMEM>>>(h1hi, h1lo, w1hi, w1lo, bih1, xp);
    gru_mma<<<NCTA, 256, GRU_SMEM>>>(xp, whhhi + WHH_SZ, whhlo + WHH_SZ, bhh1, nullptr, nullptr);
    final_linear<<<BB, 128>>>(Wlin, blin, out);
}

// round 14
// speedup vs baseline: 1.7458x; 1.1034x over previous
#include <cuda_runtime.h>
#include <cuda_fp16.h>
#include <math.h>
#include <stdint.h>

#define BB 128
#define TT 1024
#define HH 512
#define GG 1536
#define NCTA 128

// ---------------- device scratch (no allocation) ----------------
__device__ float g_xp[(size_t)BB * TT * GG];
__device__ __half g_xhi[(size_t)BB * TT * 256];
__device__ __half g_xlo[(size_t)BB * TT * 256];
__device__ __half g_h1hi[(size_t)BB * TT * HH];
__device__ __half g_h1lo[(size_t)BB * TT * HH];
__device__ __half g_w0hi[GG * 256], g_w0lo[GG * 256];
__device__ __half g_w1hi[GG * HH],  g_w1lo[GG * HH];
__device__ __half g_whhhi[2][16 * 96 * 512];
__device__ __half g_hbhi[2][BB * HH];
__device__ __half g_hblo[2][BB * HH];
// per-CTA progress flags: [mg][ng][pad 128B]; monotonic across launches/replays
__device__ unsigned g_flag[8][16][32];

// ---------------- PTX helpers (baseline PTX only) ----------------
__device__ __forceinline__ uint32_t smem_u32(const void* p) {
    uint32_t a;
    asm("{ .reg .u64 t; cvta.to.shared.u64 t, %1; cvt.u32.u64 %0, t; }" : "=r"(a) : "l"(p));
    return a;
}

#define CP16(dst, src) \
    asm volatile("cp.async.cg.shared.global [%0], [%1], 16;" :: "r"(dst), "l"(src))
#define CPCOMMIT() asm volatile("cp.async.commit_group;")
#define CPWAIT0()  asm volatile("cp.async.wait_group 0;")
#define CPWAIT1()  asm volatile("cp.async.wait_group 1;")

#define LDSM4(r, a) \
    asm volatile("ldmatrix.sync.aligned.m8n8.x4.shared.b16 {%0,%1,%2,%3}, [%4];" \
        : "=r"((r)[0]), "=r"((r)[1]), "=r"((r)[2]), "=r"((r)[3]) : "r"(a))
#define LDSM2(r, a) \
    asm volatile("ldmatrix.sync.aligned.m8n8.x2.shared.b16 {%0,%1}, [%2];" \
        : "=r"((r)[0]), "=r"((r)[1]) : "r"(a))

#define MMA16816(c, a, b) \
    asm volatile("mma.sync.aligned.m16n8k16.row.col.f32.f16.f16.f32 " \
        "{%0,%1,%2,%3}, {%4,%5,%6,%7}, {%8,%9}, {%0,%1,%2,%3};" \
        : "+f"((c)[0]), "+f"((c)[1]), "+f"((c)[2]), "+f"((c)[3]) \
        : "r"((a)[0]), "r"((a)[1]), "r"((a)[2]), "r"((a)[3]), "r"((b)[0]), "r"((b)[1]))

__device__ __forceinline__ void relstore(unsigned* p, unsigned v) {
    asm volatile("st.release.gpu.u32 [%0], %1;" :: "l"(p), "r"(v) : "memory");
}
__device__ __forceinline__ unsigned acqload(unsigned* p) {
    unsigned v;
    asm volatile("ld.acquire.gpu.u32 %0, [%1];" : "=r"(v) : "l"(p) : "memory");
    return v;
}

// ---------------- conversions ----------------
__global__ void split_f32(const float* __restrict__ src, size_t n,
                          __half* __restrict__ hi, __half* __restrict__ lo) {
    size_t i = (size_t)blockIdx.x * blockDim.x + threadIdx.x;
    if (i < n) {
        float v = src[i];
        __half h = __float2half_rn(v);
        hi[i] = h;
        lo[i] = __float2half_rn(v - __half2float(h));
    }
}

// reorder Whh [1536,512] -> [16 ng][96][512], fp16 hi only
__global__ void split_whh(const float* __restrict__ W, __half* __restrict__ hi) {
    int i = blockIdx.x * 256 + threadIdx.x;
    int k = i & 511;
    int ro = i >> 9;
    int ng = ro / 96, j = ro % 96;
    int g = j >> 5, jj = j & 31;
    hi[i] = __float2half_rn(W[(size_t)(g * 512 + ng * 32 + jj) * 512 + k]);
}

// ---------------- mma.sync GEMM, 3-pass fp16, 3-stage cp.async (round-9 structure) ----------------
template <int K>
__global__ void __launch_bounds__(256) gemm_mma(
    const __half* __restrict__ Ahi, const __half* __restrict__ Alo,
    const __half* __restrict__ Bhi, const __half* __restrict__ Blo,
    const float* __restrict__ bias, float* __restrict__ C)
{
    extern __shared__ char smx[];
    const uint32_t sb = smem_u32(smx);
    const int tid = threadIdx.x, w = tid >> 5, lane = tid & 31;
    const int wm = w >> 2, wn = w & 3;
    const int m0 = blockIdx.y * 128, n0 = blockIdx.x * 128;

    float c[4][4][4];
#pragma unroll
    for (int i = 0; i < 4; i++)
#pragma unroll
        for (int j = 0; j < 4; j++)
#pragma unroll
            for (int q = 0; q < 4; q++) c[i][j][q] = 0.f;

    const int a_r  = (lane & 7) + ((lane >> 3) & 1) * 8;
    const int a_co = lane >> 4;
    const int b_r  = lane & 7;
    const int b_co = (lane >> 3) & 1;

    const int KC = K / 64;
    const int NIT = 3 * KC;

    auto stage = [&](int it, int buf) {
        int p = it / KC;
        int kc = (it - p * KC) * 64;
        const __half* Ap = (p == 1) ? Alo : Ahi;
        const __half* Bp = (p == 2) ? Blo : Bhi;
#pragma unroll
        for (int j = 0; j < 4; j++) {
            int idx = tid + j * 256;
            int r = idx >> 3, cc = idx & 7;
            uint32_t off = (uint32_t)(r * 128 + ((cc ^ (r & 7)) << 4));
            CP16(sb + buf * 32768 + off, Ap + (size_t)(m0 + r) * K + kc + cc * 8);
            CP16(sb + buf * 32768 + 16384 + off, Bp + (size_t)(n0 + r) * K + kc + cc * 8);
        }
    };

    stage(0, 0); CPCOMMIT();
    stage(1, 1); CPCOMMIT();
    for (int it = 0; it < NIT; it++) {
        int buf = it % 3;
        CPWAIT1();
        __syncthreads();

        const uint32_t Ab = sb + buf * 32768 + (wm * 64) * 128;
        const uint32_t Bb = sb + buf * 32768 + 16384 + (wn * 32) * 128;
#pragma unroll
        for (int kk = 0; kk < 4; kk++) {
            uint32_t a[4][4];
            uint32_t asw = (uint32_t)(((2 * kk + a_co) ^ (a_r & 7)) << 4);
#pragma unroll
            for (int mt = 0; mt < 4; mt++)
                LDSM4(a[mt], Ab + (mt * 16 + a_r) * 128 + asw);
            uint32_t bsw = (uint32_t)(((2 * kk + b_co) ^ (b_r & 7)) << 4);
#pragma unroll
            for (int nt = 0; nt < 4; nt++) {
                uint32_t b[2];
                LDSM2(b, Bb + (nt * 8 + b_r) * 128 + bsw);
#pragma unroll
                for (int mt = 0; mt < 4; mt++)
                    MMA16816(c[mt][nt], a[mt], b);
            }
        }
        if (it + 2 < NIT) stage(it + 2, (it + 2) % 3);
        CPCOMMIT();
    }

#pragma unroll
    for (int nt = 0; nt < 4; nt++) {
        int col = n0 + wn * 32 + nt * 8 + (lane & 3) * 2;
        float2 bv = *(const float2*)&bias[col];
#pragma unroll
        for (int mt = 0; mt < 4; mt++) {
            int row = m0 + wm * 64 + mt * 16 + (lane >> 2);
            float2 v0 = { c[mt][nt][0] + bv.x, c[mt][nt][1] + bv.y };
            float2 v1 = { c[mt][nt][2] + bv.x, c[mt][nt][3] + bv.y };
            *(float2*)&C[(size_t)row * GG + col] = v0;
            *(float2*)&C[(size_t)(row + 8) * GG + col] = v1;
        }
    }
}

// ---------------- persistent mma.sync GRU layer (round-9 form, fp16 2-term) ----------------
// W_hh in fp16 (hi only, registers); h state as fp16 hi/lo pair.
// Per step per warp: 96 MMAs (was 144), no W-lo LDSM, no W_LO smem.
__global__ void __launch_bounds__(256, 1) gru_mma(
    const float* __restrict__ xp,
    const __half* __restrict__ Whi_g,
    const float* __restrict__ bhh,
    __half* __restrict__ seqhi, __half* __restrict__ seqlo)
{
    extern __shared__ char smx[];
    const uint32_t sb = smem_u32(smx);
    float* sbias = (float*)smx;                    // 96 floats
    const uint32_t W_HI = 512;
    const uint32_t A_HI = 512 + 98304;
    const uint32_t A_LO = A_HI + 16384;
    float* dred = (float*)(smx + W_HI);            // overlays W_HI (dead after hoist)

    const int tid = threadIdx.x, w = tid >> 5, lane = tid & 31;
    const int nq = w & 3, kh = w >> 2;
    const int half = tid >> 7;                     // == kh for this warp layout
    const int ng = blockIdx.x & 15, mg = blockIdx.x >> 4;

    const unsigned base = g_flag[mg][ng][0];       // stable between launches

    // persistent W slice, swizzled
    const __half* wh = Whi_g + (size_t)ng * 96 * 512;
    for (int idx = tid; idx < 6144; idx += 256) {
        int r = idx >> 6, cc = idx & 63;
        uint32_t off = (uint32_t)(r * 1024 + ((cc ^ (r & 7)) << 4));
        *(uint4*)(smx + W_HI + off) = *(const uint4*)(wh + r * 512 + cc * 8);
    }
    if (tid < 96) sbias[tid] = bhh[(tid >> 5) * 512 + ng * 32 + (tid & 31)];

    // zero owned region of initial state
    if (tid < 128) {
        int b = mg * 16 + (tid >> 3);
        int cc = ng * 32 + (tid & 7) * 4;
        uint2 zb = {0u, 0u};
        *(uint2*)&g_hbhi[0][b * 512 + cc] = zb;
        *(uint2*)&g_hblo[0][b * 512 + cc] = zb;
    }
    __syncthreads();

    const int a_r  = (lane & 7) + ((lane >> 3) & 1) * 8;
    const int a_co = lane >> 4;
    const int b_r  = lane & 7;
    const int b_co = (lane >> 3) & 1;
    const uint32_t AbHi = sb + A_HI + a_r * 1024;
    const uint32_t AbLo = sb + A_LO + a_r * 1024;
    uint32_t BbHi[3];
#pragma unroll
    for (int f = 0; f < 3; f++) {
        int n = nq * 24 + f * 8 + b_r;
        BbHi[f] = sb + W_HI + n * 1024;
    }

    // hoist W-hi fragments into registers (loop-invariant over all 1024 steps)
    uint32_t bhr[3][16][2];
#pragma unroll
    for (int kk0 = 0; kk0 < 16; kk0++) {
        int kk = kh * 16 + kk0;
        uint32_t bsw = (uint32_t)(((2 * kk + b_co) ^ (b_r & 7)) << 4);
#pragma unroll
        for (int f = 0; f < 3; f++)
            LDSM2(bhr[f][kk0], BbHi[f] + bsw);
    }
    __syncthreads();    // hoist reads of W_HI done before dred may overlay it

    // init-done flag (release: makes zero-init visible to group)
    if (tid == 0) relstore(&g_flag[mg][ng][0], base + 1);

    // staging mapping: thread stages chunk cc = half*32 + (tid&31), rows via j
    unsigned* myflag = &g_flag[mg][(half * 32 + (tid & 31)) >> 2][0];

    // epilogue/prefetch thread mapping
    const int b0  = tid >> 5;
    const int cc0 = tid & 31;
    const int bg0 = mg * 16 + b0;
    const int bg1 = bg0 + 8;
    const int hc0 = ng * 32 + cc0;
    const float* xpp0 = xp + (size_t)bg0 * TT * GG + hc0;
    const float* xpp1 = xp + (size_t)bg1 * TT * GG + hc0;

    for (int t = 0; t < TT; t++) {
        const int cur = t & 1, nxt = cur ^ 1;

        // prefetch xp + own hold (no inter-CTA dependency) before the flag wait
        const size_t to = (size_t)t * GG;
        float pxr0 = __ldg(xpp0 + to),        pxr1 = __ldg(xpp1 + to);
        float pxz0 = __ldg(xpp0 + to + 512),  pxz1 = __ldg(xpp1 + to + 512);
        float pxn0 = __ldg(xpp0 + to + 1024), pxn1 = __ldg(xpp1 + to + 1024);
        float phold0 = __half2float(g_hbhi[cur][bg0 * 512 + hc0])
                     + __half2float(g_hblo[cur][bg0 * 512 + hc0]);
        float phold1 = __half2float(g_hbhi[cur][bg1 * 512 + hc0])
                     + __half2float(g_hblo[cur][bg1 * 512 + hc0]);

        // per-thread wait for the single producer of this thread's chunks
        {
            const unsigned tgt = base + 1 + (unsigned)t;
            while ((int)(acqload(myflag) - tgt) < 0) { }
        }

        // stage own K-half of the h tile (16 rows x 256 cols, hi+lo)
        const __half* hh = &g_hbhi[cur][(size_t)mg * 16 * 512];
        const __half* hl = &g_hblo[cur][(size_t)mg * 16 * 512];
#pragma unroll
        for (int j = 0; j < 4; j++) {
            int idx = (tid & 127) + j * 128;
            int r = idx >> 5;                     // 0..15
            int cc = half * 32 + (idx & 31);      // own half's chunk
            uint32_t off = (uint32_t)(r * 1024 + ((cc ^ (r & 7)) << 4));
            CP16(sb + A_HI + off, hh + r * 512 + cc * 8);
            CP16(sb + A_LO + off, hl + r * 512 + cc * 8);
        }
        CPCOMMIT(); CPWAIT0();
        asm volatile("bar.sync %0, 128;" :: "r"(1 + half) : "memory");

        float acc[3][4];
#pragma unroll
        for (int f = 0; f < 3; f++)
#pragma unroll
            for (int q = 0; q < 4; q++) acc[f][q] = 0.f;

#pragma unroll
        for (int kp = 0; kp < 8; kp++) {
            int kk = kh * 16 + kp * 2;            // two K-steps per iter
            uint32_t asw0 = (uint32_t)(((2 * kk + a_co) ^ (a_r & 7)) << 4);
            uint32_t asw1 = (uint32_t)(((2 * kk + 2 + a_co) ^ (a_r & 7)) << 4);
            uint32_t ahi0[4], alo0[4], ahi1[4], alo1[4];
            LDSM4(ahi0, AbHi + asw0);
            LDSM4(alo0, AbLo + asw0);
            LDSM4(ahi1, AbHi + asw1);
            LDSM4(alo1, AbLo + asw1);
#pragma unroll
            for (int f = 0; f < 3; f++) {
                MMA16816(acc[f], ahi0, bhr[f][kp * 2]);
                MMA16816(acc[f], alo0, bhr[f][kp * 2]);
                MMA16816(acc[f], ahi1, bhr[f][kp * 2 + 1]);
                MMA16816(acc[f], alo1, bhr[f][kp * 2 + 1]);
            }
        }
        // no sync needed: dred (W_HI region) is disjoint from A LDSM reads

#pragma unroll
        for (int f = 0; f < 3; f++) {
            int colc = nq * 24 + f * 8 + (lane & 3) * 2;
            int br = lane >> 2;
            float* p0 = &dred[(kh * 16 + br) * 100 + colc];
            float* p1 = &dred[(kh * 16 + br + 8) * 100 + colc];
            p0[0] = acc[f][0]; p0[1] = acc[f][1];
            p1[0] = acc[f][2]; p1[1] = acc[f][3];
        }
        __syncthreads();

        // fused gate epilogue; keep results in regs, write state, release, then seq
        __half rhb[2], rlb[2];
#pragma unroll
        for (int pp = 0; pp < 2; pp++) {
            int b = b0 + pp * 8;
            float Dr = dred[b * 100 + cc0]      + dred[(16 + b) * 100 + cc0];
            float Dz = dred[b * 100 + 32 + cc0] + dred[(16 + b) * 100 + 32 + cc0];
            float Dn = dred[b * 100 + 64 + cc0] + dred[(16 + b) * 100 + 64 + cc0];
            float xr = pp ? pxr1 : pxr0;
            float xz = pp ? pxz1 : pxz0;
            float xn = pp ? pxn1 : pxn0;
            float hold = pp ? phold1 : phold0;
            int bg = pp ? bg1 : bg0;
            float r = __fdividef(1.f, 1.f + __expf(-(xr + Dr + sbias[cc0])));
            float z = __fdividef(1.f, 1.f + __expf(-(xz + Dz + sbias[32 + cc0])));
            float pre = xn + r * (Dn + sbias[64 + cc0]);
            float e2 = __expf(2.f * pre);
            float n = 1.f - __fdividef(2.f, e2 + 1.f);
            float hv = (1.f - z) * n + z * hold;
            __half hb = __float2half_rn(hv);
            float lo = hv - __half2float(hb);
            __half lb = __float2half_rn(lo);
            g_hbhi[nxt][bg * 512 + hc0] = hb;
            g_hblo[nxt][bg * 512 + hc0] = lb;
            rhb[pp] = hb; rlb[pp] = lb;
        }
        __syncthreads();    // h writes done before release
        if (tid == 0) relstore(&g_flag[mg][ng][0], base + 2 + (unsigned)t);

        if (seqhi) {        // history writes off the critical path
#pragma unroll
            for (int pp = 0; pp < 2; pp++) {
                int bg = pp ? bg1 : bg0;
                size_t so = ((size_t)bg * TT + t) * HH + hc0;
                seqhi[so] = rhb[pp];
                seqlo[so] = rlb[pp];
            }
        }
    }
}

// ---------------- final linear ----------------
__global__ void final_linear(const float* __restrict__ Wl, const float* __restrict__ bl,
                             float* __restrict__ out)
{
    __shared__ float ssum[4];
    int b = blockIdx.x, tid = threadIdx.x;
    float s = 0.f;
    for (int k = tid; k < 512; k += 128) {
        float hv = __half2float(g_hbhi[0][b * 512 + k])
                 + __half2float(g_hblo[0][b * 512 + k]);
        s += hv * Wl[k];
    }
#pragma unroll
    for (int o = 16; o > 0; o >>= 1) s += __shfl_down_sync(0xffffffffu, s, o);
    if ((tid & 31) == 0) ssum[tid >> 5] = s;
    __syncthreads();
    if (tid == 0) out[b] = ssum[0] + ssum[1] + ssum[2] + ssum[3] + bl[0];
}

// ---------------- launch ----------------
extern "C" void kernel_launch(void* const* d_in, const int* in_sizes, int n_in,
                              void* d_out, int out_size)
{
    const float* x    = (const float*)d_in[0];
    const float* Wih0 = (const float*)d_in[1];
    const float* Whh0 = (const float*)d_in[2];
    const float* bih0 = (const float*)d_in[3];
    const float* bhh0 = (const float*)d_in[4];
    const float* Wih1 = (const float*)d_in[5];
    const float* Whh1 = (const float*)d_in[6];
    const float* bih1 = (const float*)d_in[7];
    const float* bhh1 = (const float*)d_in[8];
    const float* Wlin = (const float*)d_in[9];
    const float* blin = (const float*)d_in[10];
    float* out = (float*)d_out;

    float* xp;
    __half *xhi, *xlo, *h1hi, *h1lo, *w0hi, *w0lo, *w1hi, *w1lo, *whhhi;
    cudaGetSymbolAddress((void**)&xp, g_xp);
    cudaGetSymbolAddress((void**)&xhi, g_xhi);
    cudaGetSymbolAddress((void**)&xlo, g_xlo);
    cudaGetSymbolAddress((void**)&h1hi, g_h1hi);
    cudaGetSymbolAddress((void**)&h1lo, g_h1lo);
    cudaGetSymbolAddress((void**)&w0hi, g_w0hi);
    cudaGetSymbolAddress((void**)&w0lo, g_w0lo);
    cudaGetSymbolAddress((void**)&w1hi, g_w1hi);
    cudaGetSymbolAddress((void**)&w1lo, g_w1lo);
    cudaGetSymbolAddress((void**)&whhhi, g_whhhi);
    const size_t WHH_SZ = 16 * 96 * 512;

    const int GEMM_SMEM = 3 * 32768;
    const int GRU_SMEM  = 512 + 98304 + 2 * 16384;          // 131584
    cudaFuncSetAttribute(gemm_mma<256>, cudaFuncAttributeMaxDynamicSharedMemorySize, GEMM_SMEM);
    cudaFuncSetAttribute(gemm_mma<512>, cudaFuncAttributeMaxDynamicSharedMemorySize, GEMM_SMEM);
    cudaFuncSetAttribute(gru_mma, cudaFuncAttributeMaxDynamicSharedMemorySize, GRU_SMEM);

    {
        size_t n = (size_t)BB * TT * 256;
        split_f32<<<(unsigned)((n + 255) / 256), 256>>>(x, n, xhi, xlo);
    }
    split_f32<<<(GG * 256 + 255) / 256, 256>>>(Wih0, (size_t)GG * 256, w0hi, w0lo);
    split_f32<<<(GG * 512 + 255) / 256, 256>>>(Wih1, (size_t)GG * 512, w1hi, w1lo);
    split_whh<<<3072, 256>>>(Whh0, whhhi);
    split_whh<<<3072, 256>>>(Whh1, whhhi + WHH_SZ);

    dim3 gg(GG / 128, (BB * TT) / 128);

    gemm_mma<256><<<gg, 256, GEMM_SMEM>>>(xhi, xlo, w0hi, w0lo, bih0, xp);
    gru_mma<<<NCTA, 256, GRU_SMEM>>>(xp, whhhi, bhh0, h1hi, h1lo);
    gemm_mma<512><<<gg, 256, GEMM_SMEM>>>(h1hi, h1lo, w1hi, w1lo, bih1, xp);
    gru_mma<<<NCTA, 256, GRU_SMEM>>>(xp, whhhi + WHH_SZ, bhh1, nullptr, nullptr);
    final_linear<<<BB, 128>>>(Wlin, blin, out);
}

// round 15
// speedup vs baseline: 1.8286x; 1.0474x over previous
#include <cuda_runtime.h>
#include <cuda_fp16.h>
#include <math.h>
#include <stdint.h>

#define BB 128
#define TT 1024
#define HH 512
#define GG 1536
#define NCTA 128

// ---------------- device scratch (no allocation) ----------------
__device__ float g_xp[(size_t)BB * TT * GG];
__device__ __half g_xhi[(size_t)BB * TT * 256];
__device__ __half g_xlo[(size_t)BB * TT * 256];
__device__ __half g_h1hi[(size_t)BB * TT * HH];
__device__ __half g_h1lo[(size_t)BB * TT * HH];
__device__ __half g_w0hi[GG * 256];
__device__ __half g_w1hi[GG * HH];
__device__ __half g_whhhi[2][16 * 96 * 512];
__device__ __half g_hbhi[2][BB * HH];
__device__ __half g_hblo[2][BB * HH];
// per-CTA progress flags: [mg][ng][pad 128B]; monotonic across launches/replays
__device__ unsigned g_flag[8][16][32];

// ---------------- PTX helpers (baseline PTX only) ----------------
__device__ __forceinline__ uint32_t smem_u32(const void* p) {
    uint32_t a;
    asm("{ .reg .u64 t; cvta.to.shared.u64 t, %1; cvt.u32.u64 %0, t; }" : "=r"(a) : "l"(p));
    return a;
}

#define CP16(dst, src) \
    asm volatile("cp.async.cg.shared.global [%0], [%1], 16;" :: "r"(dst), "l"(src))
#define CPCOMMIT() asm volatile("cp.async.commit_group;")
#define CPWAIT0()  asm volatile("cp.async.wait_group 0;")
#define CPWAIT1()  asm volatile("cp.async.wait_group 1;")

#define LDSM4(r, a) \
    asm volatile("ldmatrix.sync.aligned.m8n8.x4.shared.b16 {%0,%1,%2,%3}, [%4];" \
        : "=r"((r)[0]), "=r"((r)[1]), "=r"((r)[2]), "=r"((r)[3]) : "r"(a))
#define LDSM2(r, a) \
    asm volatile("ldmatrix.sync.aligned.m8n8.x2.shared.b16 {%0,%1}, [%2];" \
        : "=r"((r)[0]), "=r"((r)[1]) : "r"(a))

#define MMA16816(c, a, b) \
    asm volatile("mma.sync.aligned.m16n8k16.row.col.f32.f16.f16.f32 " \
        "{%0,%1,%2,%3}, {%4,%5,%6,%7}, {%8,%9}, {%0,%1,%2,%3};" \
        : "+f"((c)[0]), "+f"((c)[1]), "+f"((c)[2]), "+f"((c)[3]) \
        : "r"((a)[0]), "r"((a)[1]), "r"((a)[2]), "r"((a)[3]), "r"((b)[0]), "r"((b)[1]))

__device__ __forceinline__ void relstore(unsigned* p, unsigned v) {
    asm volatile("st.release.gpu.u32 [%0], %1;" :: "l"(p), "r"(v) : "memory");
}
__device__ __forceinline__ unsigned acqload(unsigned* p) {
    unsigned v;
    asm volatile("ld.acquire.gpu.u32 %0, [%1];" : "=r"(v) : "l"(p) : "memory");
    return v;
}

// ---------------- conversions ----------------
__global__ void split_f32(const float* __restrict__ src, size_t n,
                          __half* __restrict__ hi, __half* __restrict__ lo) {
    size_t i = (size_t)blockIdx.x * blockDim.x + threadIdx.x;
    if (i < n) {
        float v = src[i];
        __half h = __float2half_rn(v);
        hi[i] = h;
        lo[i] = __float2half_rn(v - __half2float(h));
    }
}

__global__ void to_half(const float* __restrict__ src, size_t n, __half* __restrict__ hi) {
    size_t i = (size_t)blockIdx.x * blockDim.x + threadIdx.x;
    if (i < n) hi[i] = __float2half_rn(src[i]);
}

// reorder Whh [1536,512] -> [16 ng][96][512], fp16 hi only
__global__ void split_whh(const float* __restrict__ W, __half* __restrict__ hi) {
    int i = blockIdx.x * 256 + threadIdx.x;
    int k = i & 511;
    int ro = i >> 9;
    int ng = ro / 96, j = ro % 96;
    int g = j >> 5, jj = j & 31;
    hi[i] = __float2half_rn(W[(size_t)(g * 512 + ng * 32 + jj) * 512 + k]);
}

// ---------------- mma.sync GEMM, 2-pass fp16 (Ahi*B + Alo*B), 3-stage cp.async ----------------
template <int K>
__global__ void __launch_bounds__(256) gemm_mma(
    const __half* __restrict__ Ahi, const __half* __restrict__ Alo,
    const __half* __restrict__ Bhi,
    const float* __restrict__ bias, float* __restrict__ C)
{
    extern __shared__ char smx[];
    const uint32_t sb = smem_u32(smx);
    const int tid = threadIdx.x, w = tid >> 5, lane = tid & 31;
    const int wm = w >> 2, wn = w & 3;
    const int m0 = blockIdx.y * 128, n0 = blockIdx.x * 128;

    float c[4][4][4];
#pragma unroll
    for (int i = 0; i < 4; i++)
#pragma unroll
        for (int j = 0; j < 4; j++)
#pragma unroll
            for (int q = 0; q < 4; q++) c[i][j][q] = 0.f;

    const int a_r  = (lane & 7) + ((lane >> 3) & 1) * 8;
    const int a_co = lane >> 4;
    const int b_r  = lane & 7;
    const int b_co = (lane >> 3) & 1;

    const int KC = K / 64;
    const int NIT = 2 * KC;

    auto stage = [&](int it, int buf) {
        int p = it / KC;
        int kc = (it - p * KC) * 64;
        const __half* Ap = (p == 1) ? Alo : Ahi;
#pragma unroll
        for (int j = 0; j < 4; j++) {
            int idx = tid + j * 256;
            int r = idx >> 3, cc = idx & 7;
            uint32_t off = (uint32_t)(r * 128 + ((cc ^ (r & 7)) << 4));
            CP16(sb + buf * 32768 + off, Ap + (size_t)(m0 + r) * K + kc + cc * 8);
            CP16(sb + buf * 32768 + 16384 + off, Bhi + (size_t)(n0 + r) * K + kc + cc * 8);
        }
    };

    stage(0, 0); CPCOMMIT();
    stage(1, 1); CPCOMMIT();
    for (int it = 0; it < NIT; it++) {
        int buf = it % 3;
        CPWAIT1();
        __syncthreads();

        const uint32_t Ab = sb + buf * 32768 + (wm * 64) * 128;
        const uint32_t Bb = sb + buf * 32768 + 16384 + (wn * 32) * 128;
#pragma unroll
        for (int kk = 0; kk < 4; kk++) {
            uint32_t a[4][4];
            uint32_t asw = (uint32_t)(((2 * kk + a_co) ^ (a_r & 7)) << 4);
#pragma unroll
            for (int mt = 0; mt < 4; mt++)
                LDSM4(a[mt], Ab + (mt * 16 + a_r) * 128 + asw);
            uint32_t bsw = (uint32_t)(((2 * kk + b_co) ^ (b_r & 7)) << 4);
#pragma unroll
            for (int nt = 0; nt < 4; nt++) {
                uint32_t b[2];
                LDSM2(b, Bb + (nt * 8 + b_r) * 128 + bsw);
#pragma unroll
                for (int mt = 0; mt < 4; mt++)
                    MMA16816(c[mt][nt], a[mt], b);
            }
        }
        if (it + 2 < NIT) stage(it + 2, (it + 2) % 3);
        CPCOMMIT();
    }

#pragma unroll
    for (int nt = 0; nt < 4; nt++) {
        int col = n0 + wn * 32 + nt * 8 + (lane & 3) * 2;
        float2 bv = *(const float2*)&bias[col];
#pragma unroll
        for (int mt = 0; mt < 4; mt++) {
            int row = m0 + wm * 64 + mt * 16 + (lane >> 2);
            float2 v0 = { c[mt][nt][0] + bv.x, c[mt][nt][1] + bv.y };
            float2 v1 = { c[mt][nt][2] + bv.x, c[mt][nt][3] + bv.y };
            *(float2*)&C[(size_t)row * GG + col] = v0;
            *(float2*)&C[(size_t)(row + 8) * GG + col] = v1;
        }
    }
}

// ---------------- persistent mma.sync GRU layer (round-14 form, fp16 2-term) ----------------
__global__ void __launch_bounds__(256, 1) gru_mma(
    const float* __restrict__ xp,
    const __half* __restrict__ Whi_g,
    const float* __restrict__ bhh,
    __half* __restrict__ seqhi, __half* __restrict__ seqlo)
{
    extern __shared__ char smx[];
    const uint32_t sb = smem_u32(smx);
    float* sbias = (float*)smx;                    // 96 floats
    const uint32_t W_HI = 512;
    const uint32_t A_HI = 512 + 98304;
    const uint32_t A_LO = A_HI + 16384;
    float* dred = (float*)(smx + W_HI);            // overlays W_HI (dead after hoist)

    const int tid = threadIdx.x, w = tid >> 5, lane = tid & 31;
    const int nq = w & 3, kh = w >> 2;
    const int half = tid >> 7;                     // == kh for this warp layout
    const int ng = blockIdx.x & 15, mg = blockIdx.x >> 4;

    const unsigned base = g_flag[mg][ng][0];       // stable between launches

    // persistent W slice, swizzled
    const __half* wh = Whi_g + (size_t)ng * 96 * 512;
    for (int idx = tid; idx < 6144; idx += 256) {
        int r = idx >> 6, cc = idx & 63;
        uint32_t off = (uint32_t)(r * 1024 + ((cc ^ (r & 7)) << 4));
        *(uint4*)(smx + W_HI + off) = *(const uint4*)(wh + r * 512 + cc * 8);
    }
    if (tid < 96) sbias[tid] = bhh[(tid >> 5) * 512 + ng * 32 + (tid & 31)];

    // zero owned region of initial state
    if (tid < 128) {
        int b = mg * 16 + (tid >> 3);
        int cc = ng * 32 + (tid & 7) * 4;
        uint2 zb = {0u, 0u};
        *(uint2*)&g_hbhi[0][b * 512 + cc] = zb;
        *(uint2*)&g_hblo[0][b * 512 + cc] = zb;
    }
    __syncthreads();

    const int a_r  = (lane & 7) + ((lane >> 3) & 1) * 8;
    const int a_co = lane >> 4;
    const int b_r  = lane & 7;
    const int b_co = (lane >> 3) & 1;
    const uint32_t AbHi = sb + A_HI + a_r * 1024;
    const uint32_t AbLo = sb + A_LO + a_r * 1024;
    uint32_t BbHi[3];
#pragma unroll
    for (int f = 0; f < 3; f++) {
        int n = nq * 24 + f * 8 + b_r;
        BbHi[f] = sb + W_HI + n * 1024;
    }

    // hoist W-hi fragments into registers (loop-invariant over all 1024 steps)
    uint32_t bhr[3][16][2];
#pragma unroll
    for (int kk0 = 0; kk0 < 16; kk0++) {
        int kk = kh * 16 + kk0;
        uint32_t bsw = (uint32_t)(((2 * kk + b_co) ^ (b_r & 7)) << 4);
#pragma unroll
        for (int f = 0; f < 3; f++)
            LDSM2(bhr[f][kk0], BbHi[f] + bsw);
    }
    __syncthreads();    // hoist reads of W_HI done before dred may overlay it

    // init-done flag (release: makes zero-init visible to group)
    if (tid == 0) relstore(&g_flag[mg][ng][0], base + 1);

    // staging mapping: thread stages chunk cc = half*32 + (tid&31), rows via j
    unsigned* myflag = &g_flag[mg][(half * 32 + (tid & 31)) >> 2][0];

    // epilogue/prefetch thread mapping
    const int b0  = tid >> 5;
    const int cc0 = tid & 31;
    const int bg0 = mg * 16 + b0;
    const int bg1 = bg0 + 8;
    const int hc0 = ng * 32 + cc0;
    const float* xpp0 = xp + (size_t)bg0 * TT * GG + hc0;
    const float* xpp1 = xp + (size_t)bg1 * TT * GG + hc0;

    for (int t = 0; t < TT; t++) {
        const int cur = t & 1, nxt = cur ^ 1;

        // prefetch xp + own hold (no inter-CTA dependency) before the flag wait
        const size_t to = (size_t)t * GG;
        float pxr0 = __ldg(xpp0 + to),        pxr1 = __ldg(xpp1 + to);
        float pxz0 = __ldg(xpp0 + to + 512),  pxz1 = __ldg(xpp1 + to + 512);
        float pxn0 = __ldg(xpp0 + to + 1024), pxn1 = __ldg(xpp1 + to + 1024);
        float phold0 = __half2float(g_hbhi[cur][bg0 * 512 + hc0])
                     + __half2float(g_hblo[cur][bg0 * 512 + hc0]);
        float phold1 = __half2float(g_hbhi[cur][bg1 * 512 + hc0])
                     + __half2float(g_hblo[cur][bg1 * 512 + hc0]);

        // per-thread wait for the single producer of this thread's chunks
        {
            const unsigned tgt = base + 1 + (unsigned)t;
            while ((int)(acqload(myflag) - tgt) < 0) { }
        }

        // stage own K-half of the h tile (16 rows x 256 cols, hi+lo)
        const __half* hh = &g_hbhi[cur][(size_t)mg * 16 * 512];
        const __half* hl = &g_hblo[cur][(size_t)mg * 16 * 512];
#pragma unroll
        for (int j = 0; j < 4; j++) {
            int idx = (tid & 127) + j * 128;
            int r = idx >> 5;                     // 0..15
            int cc = half * 32 + (idx & 31);      // own half's chunk
            uint32_t off = (uint32_t)(r * 1024 + ((cc ^ (r & 7)) << 4));
            CP16(sb + A_HI + off, hh + r * 512 + cc * 8);
            CP16(sb + A_LO + off, hl + r * 512 + cc * 8);
        }
        CPCOMMIT(); CPWAIT0();
        asm volatile("bar.sync %0, 128;" :: "r"(1 + half) : "memory");

        float acc[3][4];
#pragma unroll
        for (int f = 0; f < 3; f++)
#pragma unroll
            for (int q = 0; q < 4; q++) acc[f][q] = 0.f;

#pragma unroll
        for (int kp = 0; kp < 8; kp++) {
            int kk = kh * 16 + kp * 2;            // two K-steps per iter
            uint32_t asw0 = (uint32_t)(((2 * kk + a_co) ^ (a_r & 7)) << 4);
            uint32_t asw1 = (uint32_t)(((2 * kk + 2 + a_co) ^ (a_r & 7)) << 4);
            uint32_t ahi0[4], alo0[4], ahi1[4], alo1[4];
            LDSM4(ahi0, AbHi + asw0);
            LDSM4(alo0, AbLo + asw0);
            LDSM4(ahi1, AbHi + asw1);
            LDSM4(alo1, AbLo + asw1);
#pragma unroll
            for (int f = 0; f < 3; f++) {
                MMA16816(acc[f], ahi0, bhr[f][kp * 2]);
                MMA16816(acc[f], alo0, bhr[f][kp * 2]);
                MMA16816(acc[f], ahi1, bhr[f][kp * 2 + 1]);
                MMA16816(acc[f], alo1, bhr[f][kp * 2 + 1]);
            }
        }
        // no sync needed: dred (W_HI region) is disjoint from A LDSM reads

#pragma unroll
        for (int f = 0; f < 3; f++) {
            int colc = nq * 24 + f * 8 + (lane & 3) * 2;
            int br = lane >> 2;
            float* p0 = &dred[(kh * 16 + br) * 100 + colc];
            float* p1 = &dred[(kh * 16 + br + 8) * 100 + colc];
            p0[0] = acc[f][0]; p0[1] = acc[f][1];
            p1[0] = acc[f][2]; p1[1] = acc[f][3];
        }
        __syncthreads();

        // fused gate epilogue; keep results in regs, write state, release, then seq
        __half rhb[2], rlb[2];
#pragma unroll
        for (int pp = 0; pp < 2; pp++) {
            int b = b0 + pp * 8;
            float Dr = dred[b * 100 + cc0]      + dred[(16 + b) * 100 + cc0];
            float Dz = dred[b * 100 + 32 + cc0] + dred[(16 + b) * 100 + 32 + cc0];
            float Dn = dred[b * 100 + 64 + cc0] + dred[(16 + b) * 100 + 64 + cc0];
            float xr = pp ? pxr1 : pxr0;
            float xz = pp ? pxz1 : pxz0;
            float xn = pp ? pxn1 : pxn0;
            float hold = pp ? phold1 : phold0;
            int bg = pp ? bg1 : bg0;
            float r = __fdividef(1.f, 1.f + __expf(-(xr + Dr + sbias[cc0])));
            float z = __fdividef(1.f, 1.f + __expf(-(xz + Dz + sbias[32 + cc0])));
            float pre = xn + r * (Dn + sbias[64 + cc0]);
            float e2 = __expf(2.f * pre);
            float n = 1.f - __fdividef(2.f, e2 + 1.f);
            float hv = (1.f - z) * n + z * hold;
            __half hb = __float2half_rn(hv);
            float lo = hv - __half2float(hb);
            __half lb = __float2half_rn(lo);
            g_hbhi[nxt][bg * 512 + hc0] = hb;
            g_hblo[nxt][bg * 512 + hc0] = lb;
            rhb[pp] = hb; rlb[pp] = lb;
        }
        __syncthreads();    // h writes done before release
        if (tid == 0) relstore(&g_flag[mg][ng][0], base + 2 + (unsigned)t);

        if (seqhi) {        // history writes off the critical path
#pragma unroll
            for (int pp = 0; pp < 2; pp++) {
                int bg = pp ? bg1 : bg0;
                size_t so = ((size_t)bg * TT + t) * HH + hc0;
                seqhi[so] = rhb[pp];
                seqlo[so] = rlb[pp];
            }
        }
    }
}

// ---------------- final linear ----------------
__global__ void final_linear(const float* __restrict__ Wl, const float* __restrict__ bl,
                             float* __restrict__ out)
{
    __shared__ float ssum[4];
    int b = blockIdx.x, tid = threadIdx.x;
    float s = 0.f;
    for (int k = tid; k < 512; k += 128) {
        float hv = __half2float(g_hbhi[0][b * 512 + k])
                 + __half2float(g_hblo[0][b * 512 + k]);
        s += hv * Wl[k];
    }
#pragma unroll
    for (int o = 16; o > 0; o >>= 1) s += __shfl_down_sync(0xffffffffu, s, o);
    if ((tid & 31) == 0) ssum[tid >> 5] = s;
    __syncthreads();
    if (tid == 0) out[b] = ssum[0] + ssum[1] + ssum[2] + ssum[3] + bl[0];
}

// ---------------- launch ----------------
extern "C" void kernel_launch(void* const* d_in, const int* in_sizes, int n_in,
                              void* d_out, int out_size)
{
    const float* x    = (const float*)d_in[0];
    const float* Wih0 = (const float*)d_in[1];
    const float* Whh0 = (const float*)d_in[2];
    const float* bih0 = (const float*)d_in[3];
    const float* bhh0 = (const float*)d_in[4];
    const float* Wih1 = (const float*)d_in[5];
    const float* Whh1 = (const float*)d_in[6];
    const float* bih1 = (const float*)d_in[7];
    const float* bhh1 = (const float*)d_in[8];
    const float* Wlin = (const float*)d_in[9];
    const float* blin = (const float*)d_in[10];
    float* out = (float*)d_out;

    float* xp;
    __half *xhi, *xlo, *h1hi, *h1lo, *w0hi, *w1hi, *whhhi;
    cudaGetSymbolAddress((void**)&xp, g_xp);
    cudaGetSymbolAddress((void**)&xhi, g_xhi);
    cudaGetSymbolAddress((void**)&xlo, g_xlo);
    cudaGetSymbolAddress((void**)&h1hi, g_h1hi);
    cudaGetSymbolAddress((void**)&h1lo, g_h1lo);
    cudaGetSymbolAddress((void**)&w0hi, g_w0hi);
    cudaGetSymbolAddress((void**)&w1hi, g_w1hi);
    cudaGetSymbolAddress((void**)&whhhi, g_whhhi);
    const size_t WHH_SZ = 16 * 96 * 512;

    const int GEMM_SMEM = 3 * 32768;
    const int GRU_SMEM  = 512 + 98304 + 2 * 16384;          // 131584
    cudaFuncSetAttribute(gemm_mma<256>, cudaFuncAttributeMaxDynamicSharedMemorySize, GEMM_SMEM);
    cudaFuncSetAttribute(gemm_mma<512>, cudaFuncAttributeMaxDynamicSharedMemorySize, GEMM_SMEM);
    cudaFuncSetAttribute(gru_mma, cudaFuncAttributeMaxDynamicSharedMemorySize, GRU_SMEM);

    {
        size_t n = (size_t)BB * TT * 256;
        split_f32<<<(unsigned)((n + 255) / 256), 256>>>(x, n, xhi, xlo);
    }
    to_half<<<(GG * 256 + 255) / 256, 256>>>(Wih0, (size_t)GG * 256, w0hi);
    to_half<<<(GG * 512 + 255) / 256, 256>>>(Wih1, (size_t)GG * 512, w1hi);
    split_whh<<<3072, 256>>>(Whh0, whhhi);
    split_whh<<<3072, 256>>>(Whh1, whhhi + WHH_SZ);

    dim3 gg(GG / 128, (BB * TT) / 128);

    gemm_mma<256><<<gg, 256, GEMM_SMEM>>>(xhi, xlo, w0hi, bih0, xp);
    gru_mma<<<NCTA, 256, GRU_SMEM>>>(xp, whhhi, bhh0, h1hi, h1lo);
    gemm_mma<512><<<gg, 256, GEMM_SMEM>>>(h1hi, h1lo, w1hi, bih1, xp);
    gru_mma<<<NCTA, 256, GRU_SMEM>>>(xp, whhhi + WHH_SZ, bhh1, nullptr, nullptr);
    final_linear<<<BB, 128>>>(Wlin, blin, out);
}

// round 16
// speedup vs baseline: 2.3806x; 1.3019x over previous
#include <cuda_runtime.h>
#include <cuda_fp16.h>
#include <math.h>
#include <stdint.h>

#define BB 128
#define TT 1024
#define HH 512
#define GG 1536
#define NCTA 128

// ---------------- device scratch (no allocation) ----------------
__device__ float g_xp[(size_t)BB * TT * GG];
__device__ __half g_xhi[(size_t)BB * TT * 256];
__device__ __half g_h1hi[(size_t)BB * TT * HH];
__device__ __half g_w0hi[GG * 256];
__device__ __half g_w1hi[GG * HH];
__device__ __half g_whhhi[2][16 * 96 * 512];
__device__ __half g_hbhi[2][BB * HH];
__device__ __half g_hblo[2][BB * HH];
// per-CTA progress flags: [mg][ng][pad 128B]; monotonic across launches/replays
__device__ unsigned g_flag[8][16][32];

// ---------------- PTX helpers (baseline PTX only) ----------------
__device__ __forceinline__ uint32_t smem_u32(const void* p) {
    uint32_t a;
    asm("{ .reg .u64 t; cvta.to.shared.u64 t, %1; cvt.u32.u64 %0, t; }" : "=r"(a) : "l"(p));
    return a;
}

#define CP16(dst, src) \
    asm volatile("cp.async.cg.shared.global [%0], [%1], 16;" :: "r"(dst), "l"(src))
#define CPCOMMIT() asm volatile("cp.async.commit_group;")
#define CPWAIT0()  asm volatile("cp.async.wait_group 0;")
#define CPWAIT1()  asm volatile("cp.async.wait_group 1;")

#define LDSM4(r, a) \
    asm volatile("ldmatrix.sync.aligned.m8n8.x4.shared.b16 {%0,%1,%2,%3}, [%4];" \
        : "=r"((r)[0]), "=r"((r)[1]), "=r"((r)[2]), "=r"((r)[3]) : "r"(a))
#define LDSM2(r, a) \
    asm volatile("ldmatrix.sync.aligned.m8n8.x2.shared.b16 {%0,%1}, [%2];" \
        : "=r"((r)[0]), "=r"((r)[1]) : "r"(a))

#define MMA16816(c, a, b) \
    asm volatile("mma.sync.aligned.m16n8k16.row.col.f32.f16.f16.f32 " \
        "{%0,%1,%2,%3}, {%4,%5,%6,%7}, {%8,%9}, {%0,%1,%2,%3};" \
        : "+f"((c)[0]), "+f"((c)[1]), "+f"((c)[2]), "+f"((c)[3]) \
        : "r"((a)[0]), "r"((a)[1]), "r"((a)[2]), "r"((a)[3]), "r"((b)[0]), "r"((b)[1]))

__device__ __forceinline__ void relstore(unsigned* p, unsigned v) {
    asm volatile("st.release.gpu.u32 [%0], %1;" :: "l"(p), "r"(v) : "memory");
}
__device__ __forceinline__ unsigned acqload(unsigned* p) {
    unsigned v;
    asm volatile("ld.acquire.gpu.u32 %0, [%1];" : "=r"(v) : "l"(p) : "memory");
    return v;
}

// ---------------- conversions ----------------
__global__ void to_half(const float* __restrict__ src, size_t n, __half* __restrict__ hi) {
    size_t i = (size_t)blockIdx.x * blockDim.x + threadIdx.x;
    if (i < n) hi[i] = __float2half_rn(src[i]);
}

// reorder Whh [1536,512] -> [16 ng][96][512], fp16 hi only
__global__ void split_whh(const float* __restrict__ W, __half* __restrict__ hi) {
    int i = blockIdx.x * 256 + threadIdx.x;
    int k = i & 511;
    int ro = i >> 9;
    int ng = ro / 96, j = ro % 96;
    int g = j >> 5, jj = j & 31;
    hi[i] = __float2half_rn(W[(size_t)(g * 512 + ng * 32 + jj) * 512 + k]);
}

// ---------------- mma.sync GEMM, 1-pass fp16, 3-stage cp.async ----------------
template <int K>
__global__ void __launch_bounds__(256) gemm_mma(
    const __half* __restrict__ A, const __half* __restrict__ B,
    const float* __restrict__ bias, float* __restrict__ C)
{
    extern __shared__ char smx[];
    const uint32_t sb = smem_u32(smx);
    const int tid = threadIdx.x, w = tid >> 5, lane = tid & 31;
    const int wm = w >> 2, wn = w & 3;
    const int m0 = blockIdx.y * 128, n0 = blockIdx.x * 128;

    float c[4][4][4];
#pragma unroll
    for (int i = 0; i < 4; i++)
#pragma unroll
        for (int j = 0; j < 4; j++)
#pragma unroll
            for (int q = 0; q < 4; q++) c[i][j][q] = 0.f;

    const int a_r  = (lane & 7) + ((lane >> 3) & 1) * 8;
    const int a_co = lane >> 4;
    const int b_r  = lane & 7;
    const int b_co = (lane >> 3) & 1;

    const int KC = K / 64;

    auto stage = [&](int kc, int buf) {
#pragma unroll
        for (int j = 0; j < 4; j++) {
            int idx = tid + j * 256;
            int r = idx >> 3, cc = idx & 7;
            uint32_t off = (uint32_t)(r * 128 + ((cc ^ (r & 7)) << 4));
            CP16(sb + buf * 32768 + off, A + (size_t)(m0 + r) * K + kc * 64 + cc * 8);
            CP16(sb + buf * 32768 + 16384 + off, B + (size_t)(n0 + r) * K + kc * 64 + cc * 8);
        }
    };

    stage(0, 0); CPCOMMIT();
    if (KC > 1) { stage(1, 1); CPCOMMIT(); }
    for (int it = 0; it < KC; it++) {
        int buf = it % 3;
        if (it + 1 < KC) CPWAIT1(); else CPWAIT0();
        __syncthreads();

        const uint32_t Ab = sb + buf * 32768 + (wm * 64) * 128;
        const uint32_t Bb = sb + buf * 32768 + 16384 + (wn * 32) * 128;
#pragma unroll
        for (int kk = 0; kk < 4; kk++) {
            uint32_t a[4][4];
            uint32_t asw = (uint32_t)(((2 * kk + a_co) ^ (a_r & 7)) << 4);
#pragma unroll
            for (int mt = 0; mt < 4; mt++)
                LDSM4(a[mt], Ab + (mt * 16 + a_r) * 128 + asw);
            uint32_t bsw = (uint32_t)(((2 * kk + b_co) ^ (b_r & 7)) << 4);
#pragma unroll
            for (int nt = 0; nt < 4; nt++) {
                uint32_t b[2];
                LDSM2(b, Bb + (nt * 8 + b_r) * 128 + bsw);
#pragma unroll
                for (int mt = 0; mt < 4; mt++)
                    MMA16816(c[mt][nt], a[mt], b);
            }
        }
        if (it + 2 < KC) { stage(it + 2, (it + 2) % 3); }
        CPCOMMIT();
    }

#pragma unroll
    for (int nt = 0; nt < 4; nt++) {
        int col = n0 + wn * 32 + nt * 8 + (lane & 3) * 2;
        float2 bv = *(const float2*)&bias[col];
#pragma unroll
        for (int mt = 0; mt < 4; mt++) {
            int row = m0 + wm * 64 + mt * 16 + (lane >> 2);
            float2 v0 = { c[mt][nt][0] + bv.x, c[mt][nt][1] + bv.y };
            float2 v1 = { c[mt][nt][2] + bv.x, c[mt][nt][3] + bv.y };
            *(float2*)&C[(size_t)row * GG + col] = v0;
            *(float2*)&C[(size_t)(row + 8) * GG + col] = v1;
        }
    }
}

// ---------------- persistent mma.sync GRU layer (fp16 1-term matmul) ----------------
// Matmul input h quantized fp16 (hi only); state kept as fp16 hi/lo pair so the
// z*h passthrough stays ~fp32-accurate. 48 MMAs/warp/step; 16KB staging.
__global__ void __launch_bounds__(256, 1) gru_mma(
    const float* __restrict__ xp,
    const __half* __restrict__ Whi_g,
    const float* __restrict__ bhh,
    __half* __restrict__ seqhi)
{
    extern __shared__ char smx[];
    const uint32_t sb = smem_u32(smx);
    float* sbias = (float*)smx;                    // 96 floats
    const uint32_t W_HI = 512;
    const uint32_t A_HI = 512 + 98304;
    float* dred = (float*)(smx + W_HI);            // overlays W_HI (dead after hoist)

    const int tid = threadIdx.x, w = tid >> 5, lane = tid & 31;
    const int nq = w & 3, kh = w >> 2;
    const int half = tid >> 7;                     // == kh for this warp layout
    const int ng = blockIdx.x & 15, mg = blockIdx.x >> 4;

    const unsigned base = g_flag[mg][ng][0];       // stable between launches

    // persistent W slice, swizzled
    const __half* wh = Whi_g + (size_t)ng * 96 * 512;
    for (int idx = tid; idx < 6144; idx += 256) {
        int r = idx >> 6, cc = idx & 63;
        uint32_t off = (uint32_t)(r * 1024 + ((cc ^ (r & 7)) << 4));
        *(uint4*)(smx + W_HI + off) = *(const uint4*)(wh + r * 512 + cc * 8);
    }
    if (tid < 96) sbias[tid] = bhh[(tid >> 5) * 512 + ng * 32 + (tid & 31)];

    // zero owned region of initial state
    if (tid < 128) {
        int b = mg * 16 + (tid >> 3);
        int cc = ng * 32 + (tid & 7) * 4;
        uint2 zb = {0u, 0u};
        *(uint2*)&g_hbhi[0][b * 512 + cc] = zb;
        *(uint2*)&g_hblo[0][b * 512 + cc] = zb;
    }
    __syncthreads();

    const int a_r  = (lane & 7) + ((lane >> 3) & 1) * 8;
    const int a_co = lane >> 4;
    const int b_r  = lane & 7;
    const int b_co = (lane >> 3) & 1;
    const uint32_t AbHi = sb + A_HI + a_r * 1024;
    uint32_t BbHi[3];
#pragma unroll
    for (int f = 0; f < 3; f++) {
        int n = nq * 24 + f * 8 + b_r;
        BbHi[f] = sb + W_HI + n * 1024;
    }

    // hoist W-hi fragments into registers (loop-invariant over all 1024 steps)
    uint32_t bhr[3][16][2];
#pragma unroll
    for (int kk0 = 0; kk0 < 16; kk0++) {
        int kk = kh * 16 + kk0;
        uint32_t bsw = (uint32_t)(((2 * kk + b_co) ^ (b_r & 7)) << 4);
#pragma unroll
        for (int f = 0; f < 3; f++)
            LDSM2(bhr[f][kk0], BbHi[f] + bsw);
    }
    __syncthreads();    // hoist reads of W_HI done before dred may overlay it

    // init-done flag (release: makes zero-init visible to group)
    if (tid == 0) relstore(&g_flag[mg][ng][0], base + 1);

    // staging mapping: thread stages chunk cc = half*32 + (tid&31), rows via j
    unsigned* myflag = &g_flag[mg][(half * 32 + (tid & 31)) >> 2][0];

    // epilogue/prefetch thread mapping
    const int b0  = tid >> 5;
    const int cc0 = tid & 31;
    const int bg0 = mg * 16 + b0;
    const int bg1 = bg0 + 8;
    const int hc0 = ng * 32 + cc0;
    const float* xpp0 = xp + (size_t)bg0 * TT * GG + hc0;
    const float* xpp1 = xp + (size_t)bg1 * TT * GG + hc0;

    for (int t = 0; t < TT; t++) {
        const int cur = t & 1, nxt = cur ^ 1;

        // prefetch xp + own hold (no inter-CTA dependency) before the flag wait
        const size_t to = (size_t)t * GG;
        float pxr0 = __ldg(xpp0 + to),        pxr1 = __ldg(xpp1 + to);
        float pxz0 = __ldg(xpp0 + to + 512),  pxz1 = __ldg(xpp1 + to + 512);
        float pxn0 = __ldg(xpp0 + to + 1024), pxn1 = __ldg(xpp1 + to + 1024);
        float phold0 = __half2float(g_hbhi[cur][bg0 * 512 + hc0])
                     + __half2float(g_hblo[cur][bg0 * 512 + hc0]);
        float phold1 = __half2float(g_hbhi[cur][bg1 * 512 + hc0])
                     + __half2float(g_hblo[cur][bg1 * 512 + hc0]);

        // per-thread wait for the single producer of this thread's chunks
        {
            const unsigned tgt = base + 1 + (unsigned)t;
            while ((int)(acqload(myflag) - tgt) < 0) { }
        }

        // stage own K-half of the h tile (16 rows x 256 cols, hi only)
        const __half* hh = &g_hbhi[cur][(size_t)mg * 16 * 512];
#pragma unroll
        for (int j = 0; j < 4; j++) {
            int idx = (tid & 127) + j * 128;
            int r = idx >> 5;                     // 0..15
            int cc = half * 32 + (idx & 31);      // own half's chunk
            uint32_t off = (uint32_t)(r * 1024 + ((cc ^ (r & 7)) << 4));
            CP16(sb + A_HI + off, hh + r * 512 + cc * 8);
        }
        CPCOMMIT(); CPWAIT0();
        asm volatile("bar.sync %0, 128;" :: "r"(1 + half) : "memory");

        float acc[3][4];
#pragma unroll
        for (int f = 0; f < 3; f++)
#pragma unroll
            for (int q = 0; q < 4; q++) acc[f][q] = 0.f;

#pragma unroll
        for (int kp = 0; kp < 8; kp++) {
            int kk = kh * 16 + kp * 2;            // two K-steps per iter
            uint32_t asw0 = (uint32_t)(((2 * kk + a_co) ^ (a_r & 7)) << 4);
            uint32_t asw1 = (uint32_t)(((2 * kk + 2 + a_co) ^ (a_r & 7)) << 4);
            uint32_t ahi0[4], ahi1[4];
            LDSM4(ahi0, AbHi + asw0);
            LDSM4(ahi1, AbHi + asw1);
#pragma unroll
            for (int f = 0; f < 3; f++) {
                MMA16816(acc[f], ahi0, bhr[f][kp * 2]);
                MMA16816(acc[f], ahi1, bhr[f][kp * 2 + 1]);
            }
        }
        // no sync needed: dred (W_HI region) is disjoint from A LDSM reads

#pragma unroll
        for (int f = 0; f < 3; f++) {
            int colc = nq * 24 + f * 8 + (lane & 3) * 2;
            int br = lane >> 2;
            float* p0 = &dred[(kh * 16 + br) * 100 + colc];
            float* p1 = &dred[(kh * 16 + br + 8) * 100 + colc];
            p0[0] = acc[f][0]; p0[1] = acc[f][1];
            p1[0] = acc[f][2]; p1[1] = acc[f][3];
        }
        __syncthreads();

        // fused gate epilogue; keep results in regs, write state, release, then seq
        __half rhb[2];
#pragma unroll
        for (int pp = 0; pp < 2; pp++) {
            int b = b0 + pp * 8;
            float Dr = dred[b * 100 + cc0]      + dred[(16 + b) * 100 + cc0];
            float Dz = dred[b * 100 + 32 + cc0] + dred[(16 + b) * 100 + 32 + cc0];
            float Dn = dred[b * 100 + 64 + cc0] + dred[(16 + b) * 100 + 64 + cc0];
            float xr = pp ? pxr1 : pxr0;
            float xz = pp ? pxz1 : pxz0;
            float xn = pp ? pxn1 : pxn0;
            float hold = pp ? phold1 : phold0;
            int bg = pp ? bg1 : bg0;
            float r = __fdividef(1.f, 1.f + __expf(-(xr + Dr + sbias[cc0])));
            float z = __fdividef(1.f, 1.f + __expf(-(xz + Dz + sbias[32 + cc0])));
            float pre = xn + r * (Dn + sbias[64 + cc0]);
            float e2 = __expf(2.f * pre);
            float n = 1.f - __fdividef(2.f, e2 + 1.f);
            float hv = (1.f - z) * n + z * hold;
            __half hb = __float2half_rn(hv);
            __half lb = __float2half_rn(hv - __half2float(hb));
            g_hbhi[nxt][bg * 512 + hc0] = hb;
            g_hblo[nxt][bg * 512 + hc0] = lb;
            rhb[pp] = hb;
        }
        __syncthreads();    // h writes done before release
        if (tid == 0) relstore(&g_flag[mg][ng][0], base + 2 + (unsigned)t);

        if (seqhi) {        // history writes off the critical path (hi only)
#pragma unroll
            for (int pp = 0; pp < 2; pp++) {
                int bg = pp ? bg1 : bg0;
                seqhi[((size_t)bg * TT + t) * HH + hc0] = rhb[pp];
            }
        }
    }
}

// ---------------- final linear ----------------
__global__ void final_linear(const float* __restrict__ Wl, const float* __restrict__ bl,
                             float* __restrict__ out)
{
    __shared__ float ssum[4];
    int b = blockIdx.x, tid = threadIdx.x;
    float s = 0.f;
    for (int k = tid; k < 512; k += 128) {
        float hv = __half2float(g_hbhi[0][b * 512 + k])
                 + __half2float(g_hblo[0][b * 512 + k]);
        s += hv * Wl[k];
    }
#pragma unroll
    for (int o = 16; o > 0; o >>= 1) s += __shfl_down_sync(0xffffffffu, s, o);
    if ((tid & 31) == 0) ssum[tid >> 5] = s;
    __syncthreads();
    if (tid == 0) out[b] = ssum[0] + ssum[1] + ssum[2] + ssum[3] + bl[0];
}

// ---------------- launch ----------------
extern "C" void kernel_launch(void* const* d_in, const int* in_sizes, int n_in,
                              void* d_out, int out_size)
{
    const float* x    = (const float*)d_in[0];
    const float* Wih0 = (const float*)d_in[1];
    const float* Whh0 = (const float*)d_in[2];
    const float* bih0 = (const float*)d_in[3];
    const float* bhh0 = (const float*)d_in[4];
    const float* Wih1 = (const float*)d_in[5];
    const float* Whh1 = (const float*)d_in[6];
    const float* bih1 = (const float*)d_in[7];
    const float* bhh1 = (const float*)d_in[8];
    const float* Wlin = (const float*)d_in[9];
    const float* blin = (const float*)d_in[10];
    float* out = (float*)d_out;

    float* xp;
    __half *xhi, *h1hi, *w0hi, *w1hi, *whhhi;
    cudaGetSymbolAddress((void**)&xp, g_xp);
    cudaGetSymbolAddress((void**)&xhi, g_xhi);
    cudaGetSymbolAddress((void**)&h1hi, g_h1hi);
    cudaGetSymbolAddress((void**)&w0hi, g_w0hi);
    cudaGetSymbolAddress((void**)&w1hi, g_w1hi);
    cudaGetSymbolAddress((void**)&whhhi, g_whhhi);
    const size_t WHH_SZ = 16 * 96 * 512;

    const int GEMM_SMEM = 3 * 32768;
    const int GRU_SMEM  = 512 + 98304 + 16384;              // 115200
    cudaFuncSetAttribute(gemm_mma<256>, cudaFuncAttributeMaxDynamicSharedMemorySize, GEMM_SMEM);
    cudaFuncSetAttribute(gemm_mma<512>, cudaFuncAttributeMaxDynamicSharedMemorySize, GEMM_SMEM);
    cudaFuncSetAttribute(gru_mma, cudaFuncAttributeMaxDynamicSharedMemorySize, GRU_SMEM);

    {
        size_t n = (size_t)BB * TT * 256;
        to_half<<<(unsigned)((n + 255) / 256), 256>>>(x, n, xhi);
    }
    to_half<<<(GG * 256 + 255) / 256, 256>>>(Wih0, (size_t)GG * 256, w0hi);
    to_half<<<(GG * 512 + 255) / 256, 256>>>(Wih1, (size_t)GG * 512, w1hi);
    split_whh<<<3072, 256>>>(Whh0, whhhi);
    split_whh<<<3072, 256>>>(Whh1, whhhi + WHH_SZ);

    dim3 gg(GG / 128, (BB * TT) / 128);

    gemm_mma<256><<<gg, 256, GEMM_SMEM>>>(xhi, w0hi, bih0, xp);
    gru_mma<<<NCTA, 256, GRU_SMEM>>>(xp, whhhi, bhh0, h1hi);
    gemm_mma<512><<<gg, 256, GEMM_SMEM>>>(h1hi, w1hi, bih1, xp);
    gru_mma<<<NCTA, 256, GRU_SMEM>>>(xp, whhhi + WHH_SZ, bhh1, nullptr);
    final_linear<<<BB, 128>>>(Wlin, blin, out);
}

// round 17
// speedup vs baseline: 3.1922x; 1.3409x over previous
#include <cuda_runtime.h>
#include <cuda_fp16.h>
#include <math.h>
#include <stdint.h>

#define BB 128
#define TT 1024
#define HH 512
#define GG 1536
#define NCTA 128

// ---------------- device scratch (no allocation) ----------------
__device__ float g_xp[(size_t)BB * TT * GG];        // layer-0 input projections
__device__ __half g_xhi[(size_t)BB * TT * 256];
__device__ __half g_w0hi[GG * 256];
__device__ __half g_whh0s[16 * 96 * 512];           // Whh0 reordered slices
__device__ __half g_wih1s[16 * 96 * 512];           // Wih1 reordered slices
__device__ __half g_whh1s[16 * 96 * 512];           // Whh1 reordered slices
__device__ __half g_h0hi[2][BB * HH];               // layer-0 state hi/lo
__device__ __half g_h0lo[2][BB * HH];
__device__ __half g_h1hi[2][BB * HH];               // layer-1 state hi/lo
__device__ __half g_h1lo[2][BB * HH];
// per-CTA progress flags: [mg][ng][pad 128B]; monotonic across launches/replays
__device__ unsigned g_flag[8][16][32];

// ---------------- PTX helpers (baseline PTX only) ----------------
__device__ __forceinline__ uint32_t smem_u32(const void* p) {
    uint32_t a;
    asm("{ .reg .u64 t; cvta.to.shared.u64 t, %1; cvt.u32.u64 %0, t; }" : "=r"(a) : "l"(p));
    return a;
}

#define CP16(dst, src) \
    asm volatile("cp.async.cg.shared.global [%0], [%1], 16;" :: "r"(dst), "l"(src))
#define CPCOMMIT() asm volatile("cp.async.commit_group;")
#define CPWAIT0()  asm volatile("cp.async.wait_group 0;")
#define CPWAIT1()  asm volatile("cp.async.wait_group 1;")

#define LDSM4(r, a) \
    asm volatile("ldmatrix.sync.aligned.m8n8.x4.shared.b16 {%0,%1,%2,%3}, [%4];" \
        : "=r"((r)[0]), "=r"((r)[1]), "=r"((r)[2]), "=r"((r)[3]) : "r"(a))
#define LDSM2(r, a) \
    asm volatile("ldmatrix.sync.aligned.m8n8.x2.shared.b16 {%0,%1}, [%2];" \
        : "=r"((r)[0]), "=r"((r)[1]) : "r"(a))

#define MMA16816(c, a, b) \
    asm volatile("mma.sync.aligned.m16n8k16.row.col.f32.f16.f16.f32 " \
        "{%0,%1,%2,%3}, {%4,%5,%6,%7}, {%8,%9}, {%0,%1,%2,%3};" \
        : "+f"((c)[0]), "+f"((c)[1]), "+f"((c)[2]), "+f"((c)[3]) \
        : "r"((a)[0]), "r"((a)[1]), "r"((a)[2]), "r"((a)[3]), "r"((b)[0]), "r"((b)[1]))

__device__ __forceinline__ void relstore(unsigned* p, unsigned v) {
    asm volatile("st.release.gpu.u32 [%0], %1;" :: "l"(p), "r"(v) : "memory");
}
__device__ __forceinline__ unsigned acqload(unsigned* p) {
    unsigned v;
    asm volatile("ld.acquire.gpu.u32 %0, [%1];" : "=r"(v) : "l"(p) : "memory");
    return v;
}

// ---------------- conversions ----------------
__global__ void to_half(const float* __restrict__ src, size_t n, __half* __restrict__ hi) {
    size_t i = (size_t)blockIdx.x * blockDim.x + threadIdx.x;
    if (i < n) hi[i] = __float2half_rn(src[i]);
}

// reorder W [1536,512] -> [16 ng][96][512], fp16
__global__ void split_whh(const float* __restrict__ W, __half* __restrict__ hi) {
    int i = blockIdx.x * 256 + threadIdx.x;
    int k = i & 511;
    int ro = i >> 9;
    int ng = ro / 96, j = ro % 96;
    int g = j >> 5, jj = j & 31;
    hi[i] = __float2half_rn(W[(size_t)(g * 512 + ng * 32 + jj) * 512 + k]);
}

// ---------------- mma.sync GEMM, 1-pass fp16, 3-stage cp.async (layer-0 proj only) ----------------
template <int K>
__global__ void __launch_bounds__(256) gemm_mma(
    const __half* __restrict__ A, const __half* __restrict__ B,
    const float* __restrict__ bias, float* __restrict__ C)
{
    extern __shared__ char smx[];
    const uint32_t sb = smem_u32(smx);
    const int tid = threadIdx.x, w = tid >> 5, lane = tid & 31;
    const int wm = w >> 2, wn = w & 3;
    const int m0 = blockIdx.y * 128, n0 = blockIdx.x * 128;

    float c[4][4][4];
#pragma unroll
    for (int i = 0; i < 4; i++)
#pragma unroll
        for (int j = 0; j < 4; j++)
#pragma unroll
            for (int q = 0; q < 4; q++) c[i][j][q] = 0.f;

    const int a_r  = (lane & 7) + ((lane >> 3) & 1) * 8;
    const int a_co = lane >> 4;
    const int b_r  = lane & 7;
    const int b_co = (lane >> 3) & 1;

    const int KC = K / 64;

    auto stage = [&](int kc, int buf) {
#pragma unroll
        for (int j = 0; j < 4; j++) {
            int idx = tid + j * 256;
            int r = idx >> 3, cc = idx & 7;
            uint32_t off = (uint32_t)(r * 128 + ((cc ^ (r & 7)) << 4));
            CP16(sb + buf * 32768 + off, A + (size_t)(m0 + r) * K + kc * 64 + cc * 8);
            CP16(sb + buf * 32768 + 16384 + off, B + (size_t)(n0 + r) * K + kc * 64 + cc * 8);
        }
    };

    stage(0, 0); CPCOMMIT();
    if (KC > 1) { stage(1, 1); CPCOMMIT(); }
    for (int it = 0; it < KC; it++) {
        int buf = it % 3;
        if (it + 1 < KC) CPWAIT1(); else CPWAIT0();
        __syncthreads();

        const uint32_t Ab = sb + buf * 32768 + (wm * 64) * 128;
        const uint32_t Bb = sb + buf * 32768 + 16384 + (wn * 32) * 128;
#pragma unroll
        for (int kk = 0; kk < 4; kk++) {
            uint32_t a[4][4];
            uint32_t asw = (uint32_t)(((2 * kk + a_co) ^ (a_r & 7)) << 4);
#pragma unroll
            for (int mt = 0; mt < 4; mt++)
                LDSM4(a[mt], Ab + (mt * 16 + a_r) * 128 + asw);
            uint32_t bsw = (uint32_t)(((2 * kk + b_co) ^ (b_r & 7)) << 4);
#pragma unroll
            for (int nt = 0; nt < 4; nt++) {
                uint32_t b[2];
                LDSM2(b, Bb + (nt * 8 + b_r) * 128 + bsw);
#pragma unroll
                for (int mt = 0; mt < 4; mt++)
                    MMA16816(c[mt][nt], a[mt], b);
            }
        }
        if (it + 2 < KC) { stage(it + 2, (it + 2) % 3); }
        CPCOMMIT();
    }

#pragma unroll
    for (int nt = 0; nt < 4; nt++) {
        int col = n0 + wn * 32 + nt * 8 + (lane & 3) * 2;
        float2 bv = *(const float2*)&bias[col];
#pragma unroll
        for (int mt = 0; mt < 4; mt++) {
            int row = m0 + wm * 64 + mt * 16 + (lane >> 2);
            float2 v0 = { c[mt][nt][0] + bv.x, c[mt][nt][1] + bv.y };
            float2 v1 = { c[mt][nt][2] + bv.x, c[mt][nt][3] + bv.y };
            *(float2*)&C[(size_t)row * GG + col] = v0;
            *(float2*)&C[(size_t)(row + 8) * GG + col] = v1;
        }
    }
}

// ---------------- fused 2-layer persistent GRU ----------------
// Fused round t in [0, TT]: phase A = layer-0 step t (t<TT), phase B = layer-1
// step t-1 (t>=1). Layer-1's input projection xp1 = h0[t-1] @ Wih1^T is computed
// in-loop sharing the staged A0 tile (Wih1 fragments hoisted to registers).
// One flag release per round covers h0[t] and h1[t-1]. 1025 sync rounds total.
__global__ void __launch_bounds__(256, 1) gru_fused(
    const float* __restrict__ xp,
    const __half* __restrict__ Whh0g, const __half* __restrict__ Wih1g,
    const __half* __restrict__ Whh1g,
    const float* __restrict__ bhh0, const float* __restrict__ bih1,
    const float* __restrict__ bhh1)
{
    extern __shared__ char smx[];
    const uint32_t sb = smem_u32(smx);
    float* sbias = (float*)smx;                    // [0,96) bhh0 | [96,192) bih1 | [192,288) bhh1
    const uint32_t W0 = 1536;                      // Whh0 slice, 98304 B
    const uint32_t W1 = 1536 + 98304;              // Wih1 (init) then Whh1 slice
    const uint32_t A0 = W1 + 98304;                // h0 tile, 16384 B
    const uint32_t A1 = A0 + 16384;                // h1 tile, 16384 B
    float* dredA = (float*)(smx + A0);             // reduction overlay (A dead post-MMA)
    float* dredB = (float*)(smx + A1);

    const int tid = threadIdx.x, w = tid >> 5, lane = tid & 31;
    const int nq = w & 3, kh = w >> 2;
    const int half = tid >> 7;
    const int ng = blockIdx.x & 15, mg = blockIdx.x >> 4;

    const unsigned base = g_flag[mg][ng][0];

    const int a_r  = (lane & 7) + ((lane >> 3) & 1) * 8;
    const int a_co = lane >> 4;
    const int b_r  = lane & 7;
    const int b_co = (lane >> 3) & 1;
    const int b_m  = lane >> 3;

    // ---- init: Wih1 -> W1 region -> hoist to regs -> overwrite with Whh1 ----
    const __half* wi1 = Wih1g + (size_t)ng * 96 * 512;
    for (int idx = tid; idx < 6144; idx += 256) {
        int r = idx >> 6, cc = idx & 63;
        uint32_t off = (uint32_t)(r * 1024 + ((cc ^ (r & 7)) << 4));
        *(uint4*)(smx + W1 + off) = *(const uint4*)(wi1 + r * 512 + cc * 8);
    }
    __syncthreads();

    uint32_t bih[3][16][2];                        // Wih1 fragments (persistent)
#pragma unroll
    for (int kk0 = 0; kk0 < 16; kk0++) {
        int kk = kh * 16 + kk0;
        uint32_t bsw = (uint32_t)(((2 * kk + b_co) ^ (b_r & 7)) << 4);
#pragma unroll
        for (int f = 0; f < 3; f++)
            LDSM2(bih[f][kk0], sb + W1 + (nq * 24 + f * 8 + b_r) * 1024 + bsw);
    }
    __syncthreads();

    const __half* wh0 = Whh0g + (size_t)ng * 96 * 512;
    const __half* wh1 = Whh1g + (size_t)ng * 96 * 512;
    for (int idx = tid; idx < 6144; idx += 256) {
        int r = idx >> 6, cc = idx & 63;
        uint32_t off = (uint32_t)(r * 1024 + ((cc ^ (r & 7)) << 4));
        *(uint4*)(smx + W0 + off) = *(const uint4*)(wh0 + r * 512 + cc * 8);
        *(uint4*)(smx + W1 + off) = *(const uint4*)(wh1 + r * 512 + cc * 8);
    }
    if (tid < 96) {
        int g = tid >> 5, jj = tid & 31;
        sbias[tid]       = bhh0[g * 512 + ng * 32 + jj];
        sbias[96 + tid]  = bih1[g * 512 + ng * 32 + jj];
        sbias[192 + tid] = bhh1[g * 512 + ng * 32 + jj];
    }
    // zero owned state: h0 buf[0]; h1 buf[0] and buf[1]
    if (tid < 128) {
        int b = mg * 16 + (tid >> 3);
        int cc = ng * 32 + (tid & 7) * 4;
        uint2 zb = {0u, 0u};
        *(uint2*)&g_h0hi[0][b * 512 + cc] = zb;
        *(uint2*)&g_h0lo[0][b * 512 + cc] = zb;
        *(uint2*)&g_h1hi[0][b * 512 + cc] = zb;
        *(uint2*)&g_h1lo[0][b * 512 + cc] = zb;
        *(uint2*)&g_h1hi[1][b * 512 + cc] = zb;
        *(uint2*)&g_h1lo[1][b * 512 + cc] = zb;
    }
    __syncthreads();
    if (tid == 0) relstore(&g_flag[mg][ng][0], base + 1);

    const uint32_t Ab0 = sb + A0 + a_r * 1024;
    const uint32_t Ab1 = sb + A1 + a_r * 1024;
    uint32_t Bw0[3], Bw1[3];
#pragma unroll
    for (int f = 0; f < 3; f++) {
        int n = nq * 24 + f * 8 + b_r;
        Bw0[f] = sb + W0 + n * 1024;
        Bw1[f] = sb + W1 + n * 1024;
    }

    unsigned* myflag = &g_flag[mg][(half * 32 + (tid & 31)) >> 2][0];

    const int b0  = tid >> 5;
    const int cc0 = tid & 31;
    const int bg0 = mg * 16 + b0;
    const int bg1 = bg0 + 8;
    const int hc0 = ng * 32 + cc0;
    const float* xpp0 = xp + (size_t)bg0 * TT * GG + hc0;
    const float* xpp1 = xp + (size_t)bg1 * TT * GG + hc0;

    for (int t = 0; t <= TT; t++) {
        const int cur0 = t & 1, nxt0 = cur0 ^ 1;   // h0[t-1] read / h0[t] write
        const int cur1 = t & 1;                    // h1[t-2] read
        const int wr1  = (t + 1) & 1;              // h1[t-1] write

        // prefetch xp0 (clamped at t=TT) + own holds (self-produced columns)
        const size_t to = (size_t)(t < TT ? t : TT - 1) * GG;
        float pxr0 = __ldg(xpp0 + to),        pxr1 = __ldg(xpp1 + to);
        float pxz0 = __ldg(xpp0 + to + 512),  pxz1 = __ldg(xpp1 + to + 512);
        float pxn0 = __ldg(xpp0 + to + 1024), pxn1 = __ldg(xpp1 + to + 1024);
        float ph0a = __half2float(g_h0hi[cur0][bg0 * 512 + hc0])
                   + __half2float(g_h0lo[cur0][bg0 * 512 + hc0]);
        float ph0b = __half2float(g_h0hi[cur0][bg1 * 512 + hc0])
                   + __half2float(g_h0lo[cur0][bg1 * 512 + hc0]);
        float ph1a = __half2float(g_h1hi[cur1][bg0 * 512 + hc0])
                   + __half2float(g_h1lo[cur1][bg0 * 512 + hc0]);
        float ph1b = __half2float(g_h1hi[cur1][bg1 * 512 + hc0])
                   + __half2float(g_h1lo[cur1][bg1 * 512 + hc0]);

        // wait for the single producer of this thread's chunks (covers h0 & h1)
        {
            const unsigned tgt = base + 1 + (unsigned)t;
            while ((int)(acqload(myflag) - tgt) < 0) { }
        }

        // stage own K-half of h0[t-1] and h1[t-2] tiles
        const __half* s0 = &g_h0hi[cur0][(size_t)mg * 16 * 512];
        const __half* s1 = &g_h1hi[cur1][(size_t)mg * 16 * 512];
#pragma unroll
        for (int j = 0; j < 4; j++) {
            int idx = (tid & 127) + j * 128;
            int r = idx >> 5;
            int cc = half * 32 + (idx & 31);
            uint32_t off = (uint32_t)(r * 1024 + ((cc ^ (r & 7)) << 4));
            CP16(sb + A0 + off, s0 + r * 512 + cc * 8);
            CP16(sb + A1 + off, s1 + r * 512 + cc * 8);
        }
        CPCOMMIT(); CPWAIT0();
        asm volatile("bar.sync %0, 128;" :: "r"(1 + half) : "memory");

        float d0[3][4], x1[3][4], d1[3][4];
#pragma unroll
        for (int f = 0; f < 3; f++)
#pragma unroll
            for (int q = 0; q < 4; q++) { d0[f][q] = 0.f; x1[f][q] = 0.f; d1[f][q] = 0.f; }

#pragma unroll
        for (int kp = 0; kp < 8; kp++) {
            int kk = kh * 16 + kp * 2;
            uint32_t asw0 = (uint32_t)(((2 * kk + a_co) ^ (a_r & 7)) << 4);
            uint32_t asw1 = (uint32_t)(((2 * kk + 2 + a_co) ^ (a_r & 7)) << 4);
            uint32_t a00[4], a01[4], a10[4], a11[4];
            LDSM4(a00, Ab0 + asw0);
            LDSM4(a01, Ab0 + asw1);
            LDSM4(a10, Ab1 + asw0);
            LDSM4(a11, Ab1 + asw1);
            uint32_t bsw = (uint32_t)(((2 * kk + b_m) ^ (b_r & 7)) << 4);
#pragma unroll
            for (int f = 0; f < 3; f++) {
                uint32_t w0[4], w1[4];
                LDSM4(w0, Bw0[f] + bsw);
                LDSM4(w1, Bw1[f] + bsw);
                MMA16816(d0[f], a00, w0);
                MMA16816(d0[f], a01, w0 + 2);
                MMA16816(x1[f], a00, bih[f][kp * 2]);
                MMA16816(x1[f], a01, bih[f][kp * 2 + 1]);
                MMA16816(d1[f], a10, w1);
                MMA16816(d1[f], a11, w1 + 2);
            }
        }
        __syncthreads();    // all LDSMs of A0/A1 done before dred overlays them

        const int colc = nq * 24 + ((lane & 3) * 2);
        const int br = lane >> 2;
        // wave 1: D0 partials
#pragma unroll
        for (int f = 0; f < 3; f++) {
            float* p0 = &dredA[(kh * 16 + br) * 100 + colc + f * 8];
            float* p1 = &dredA[(kh * 16 + br + 8) * 100 + colc + f * 8];
            p0[0] = d0[f][0]; p0[1] = d0[f][1];
            p1[0] = d0[f][2]; p1[1] = d0[f][3];
        }
        __syncthreads();

        // layer-0 epilogue
        if (t < TT) {
#pragma unroll
            for (int pp = 0; pp < 2; pp++) {
                int b = b0 + pp * 8;
                float Dr = dredA[b * 100 + cc0]      + dredA[(16 + b) * 100 + cc0];
                float Dz = dredA[b * 100 + 32 + cc0] + dredA[(16 + b) * 100 + 32 + cc0];
                float Dn = dredA[b * 100 + 64 + cc0] + dredA[(16 + b) * 100 + 64 + cc0];
                float xr = pp ? pxr1 : pxr0;
                float xz = pp ? pxz1 : pxz0;
                float xn = pp ? pxn1 : pxn0;
                float hold = pp ? ph0b : ph0a;
                int bg = pp ? bg1 : bg0;
                float r = __fdividef(1.f, 1.f + __expf(-(xr + Dr + sbias[cc0])));
                float z = __fdividef(1.f, 1.f + __expf(-(xz + Dz + sbias[32 + cc0])));
                float pre = xn + r * (Dn + sbias[64 + cc0]);
                float e2 = __expf(2.f * pre);
                float n = 1.f - __fdividef(2.f, e2 + 1.f);
                float hv = (1.f - z) * n + z * hold;
                __half hb = __float2half_rn(hv);
                __half lb = __float2half_rn(hv - __half2float(hb));
                g_h0hi[nxt0][bg * 512 + hc0] = hb;
                g_h0lo[nxt0][bg * 512 + hc0] = lb;
            }
        }
        __syncthreads();    // dredA reads done before wave 2 overwrites

        // wave 2: XP1 -> dredA, D1 -> dredB
#pragma unroll
        for (int f = 0; f < 3; f++) {
            float* a0p = &dredA[(kh * 16 + br) * 100 + colc + f * 8];
            float* a1p = &dredA[(kh * 16 + br + 8) * 100 + colc + f * 8];
            a0p[0] = x1[f][0]; a0p[1] = x1[f][1];
            a1p[0] = x1[f][2]; a1p[1] = x1[f][3];
            float* b0p = &dredB[(kh * 16 + br) * 100 + colc + f * 8];
            float* b1p = &dredB[(kh * 16 + br + 8) * 100 + colc + f * 8];
            b0p[0] = d1[f][0]; b0p[1] = d1[f][1];
            b1p[0] = d1[f][2]; b1p[1] = d1[f][3];
        }
        __syncthreads();

        // layer-1 epilogue (step t-1)
        if (t >= 1) {
#pragma unroll
            for (int pp = 0; pp < 2; pp++) {
                int b = b0 + pp * 8;
                float Xr = dredA[b * 100 + cc0]      + dredA[(16 + b) * 100 + cc0] + sbias[96 + cc0];
                float Xz = dredA[b * 100 + 32 + cc0] + dredA[(16 + b) * 100 + 32 + cc0] + sbias[128 + cc0];
                float Xn = dredA[b * 100 + 64 + cc0] + dredA[(16 + b) * 100 + 64 + cc0] + sbias[160 + cc0];
                float Dr = dredB[b * 100 + cc0]      + dredB[(16 + b) * 100 + cc0];
                float Dz = dredB[b * 100 + 32 + cc0] + dredB[(16 + b) * 100 + 32 + cc0];
                float Dn = dredB[b * 100 + 64 + cc0] + dredB[(16 + b) * 100 + 64 + cc0];
                float hold = pp ? ph1b : ph1a;
                int bg = pp ? bg1 : bg0;
                float r = __fdividef(1.f, 1.f + __expf(-(Xr + Dr + sbias[192 + cc0])));
                float z = __fdividef(1.f, 1.f + __expf(-(Xz + Dz + sbias[224 + cc0])));
                float pre = Xn + r * (Dn + sbias[256 + cc0]);
                float e2 = __expf(2.f * pre);
                float n = 1.f - __fdividef(2.f, e2 + 1.f);
                float hv = (1.f - z) * n + z * hold;
                __half hb = __float2half_rn(hv);
                __half lb = __float2half_rn(hv - __half2float(hb));
                g_h1hi[wr1][bg * 512 + hc0] = hb;
                g_h1lo[wr1][bg * 512 + hc0] = lb;
            }
        }
        __syncthreads();    // all state writes done before release
        if (tid == 0) relstore(&g_flag[mg][ng][0], base + 2 + (unsigned)t);
    }
}

// ---------------- final linear: h1[1023] lives in buf index 1 ----------------
__global__ void final_linear(const float* __restrict__ Wl, const float* __restrict__ bl,
                             float* __restrict__ out)
{
    __shared__ float ssum[4];
    int b = blockIdx.x, tid = threadIdx.x;
    float s = 0.f;
    for (int k = tid; k < 512; k += 128) {
        float hv = __half2float(g_h1hi[1][b * 512 + k])
                 + __half2float(g_h1lo[1][b * 512 + k]);
        s += hv * Wl[k];
    }
#pragma unroll
    for (int o = 16; o > 0; o >>= 1) s += __shfl_down_sync(0xffffffffu, s, o);
    if ((tid & 31) == 0) ssum[tid >> 5] = s;
    __syncthreads();
    if (tid == 0) out[b] = ssum[0] + ssum[1] + ssum[2] + ssum[3] + bl[0];
}

// ---------------- launch ----------------
extern "C" void kernel_launch(void* const* d_in, const int* in_sizes, int n_in,
                              void* d_out, int out_size)
{
    const float* x    = (const float*)d_in[0];
    const float* Wih0 = (const float*)d_in[1];
    const float* Whh0 = (const float*)d_in[2];
    const float* bih0 = (const float*)d_in[3];
    const float* bhh0 = (const float*)d_in[4];
    const float* Wih1 = (const float*)d_in[5];
    const float* Whh1 = (const float*)d_in[6];
    const float* bih1 = (const float*)d_in[7];
    const float* bhh1 = (const float*)d_in[8];
    const float* Wlin = (const float*)d_in[9];
    const float* blin = (const float*)d_in[10];
    float* out = (float*)d_out;

    float* xp;
    __half *xhi, *w0hi, *whh0s, *wih1s, *whh1s;
    cudaGetSymbolAddress((void**)&xp, g_xp);
    cudaGetSymbolAddress((void**)&xhi, g_xhi);
    cudaGetSymbolAddress((void**)&w0hi, g_w0hi);
    cudaGetSymbolAddress((void**)&whh0s, g_whh0s);
    cudaGetSymbolAddress((void**)&wih1s, g_wih1s);
    cudaGetSymbolAddress((void**)&whh1s, g_whh1s);

    const int GEMM_SMEM = 3 * 32768;
    const int FUSED_SMEM = 1536 + 2 * 98304 + 2 * 16384;    // 230912
    cudaFuncSetAttribute(gemm_mma<256>, cudaFuncAttributeMaxDynamicSharedMemorySize, GEMM_SMEM);
    cudaFuncSetAttribute(gru_fused, cudaFuncAttributeMaxDynamicSharedMemorySize, FUSED_SMEM);

    {
        size_t n = (size_t)BB * TT * 256;
        to_half<<<(unsigned)((n + 255) / 256), 256>>>(x, n, xhi);
    }
    to_half<<<(GG * 256 + 255) / 256, 256>>>(Wih0, (size_t)GG * 256, w0hi);
    split_whh<<<3072, 256>>>(Whh0, whh0s);
    split_whh<<<3072, 256>>>(Wih1, wih1s);
    split_whh<<<3072, 256>>>(Whh1, whh1s);

    dim3 gg(GG / 128, (BB * TT) / 128);

    gemm_mma<256><<<gg, 256, GEMM_SMEM>>>(xhi, w0hi, bih0, xp);
    gru_fused<<<NCTA, 256, FUSED_SMEM>>>(xp, whh0s, wih1s, whh1s, bhh0, bih1, bhh1);
    final_linear<<<BB, 128>>>(Wlin, blin, out);
}